// round 13
// baseline (speedup 1.0000x reference)
#include <cuda_runtime.h>
#include <cuda_bf16.h>
#include <cstdint>
#include <math.h>

// ---------------- problem constants ----------------
#define BATCH 4
#define IMGH 128
#define IMGW 128
#define NTOKS (IMGH*IMGW)
#define TOT (BATCH*NTOKS)
#define DIM 192
#define H3 576
#define NHEAD 6
#define HD 32
#define WS 16
#define SS 8
#define NWIN 64
#define WIN 256
#define NDICT 64
#define RD 10
#define DTD 64
#define MLPH 384
#define CH 448
#define GS 128
#define NG 128
#define YC 384

// ---------------- scratch ----------------
__device__ __align__(16) float g_xn  [TOT*DIM];
__device__ __align__(16) float g_qkv [TOT*H3];
__device__ __align__(16) float g_q   [TOT*RD];
__device__ __align__(16) float g_kn  [BATCH*NDICT*RD];
__device__ __align__(16) float g_v   [BATCH*NDICT*DIM];
__device__ __align__(16) float g_tdf [BATCH*NDICT*DTD];
__device__ __align__(16) float g_sim [TOT*NDICT];
__device__           int   g_tkid[TOT];
__device__           int   g_sidx[TOT];
__device__           int   g_off [BATCH*NDICT];
__device__ __align__(16) float g_ycat[TOT*YC];
__device__ __align__(16) float g_xs  [TOT*DIM];
__device__ __align__(16) float g_rpbT[NHEAD*WIN*WIN];
__device__ __align__(16) float g_xc  [TOT*CH];
__device__ __align__(16) float g_s   [TOT*CH];
__device__ __align__(16) float g_bcat[YC*DIM];
__device__ __align__(16) float g_bcatb[DIM];

// ---------------- side stream for fork/join (created at static init) ----------------
static cudaStream_t g_s2 = nullptr;
static cudaEvent_t g_ev1 = nullptr, g_ev2 = nullptr;
namespace {
struct StreamInit {
    StreamInit() {
        if (cudaStreamCreateWithFlags(&g_s2, cudaStreamNonBlocking) != cudaSuccess) g_s2 = nullptr;
        if (cudaEventCreateWithFlags(&g_ev1, cudaEventDisableTiming) != cudaSuccess) g_ev1 = nullptr;
        if (cudaEventCreateWithFlags(&g_ev2, cudaEventDisableTiming) != cudaSuccess) g_ev2 = nullptr;
    }
};
StreamInit g_stream_init;
}

// ---------------- device helpers ----------------
__device__ __forceinline__ float fexp(float x) {
    x = fmaxf(x, -80.0f);
    float t = x * 1.4426950408889634f;
    float r = rintf(t);
    float f = t - r;
    float p = 1.3333558146e-3f;
    p = fmaf(p, f, 9.6181291076e-3f);
    p = fmaf(p, f, 5.5504108665e-2f);
    p = fmaf(p, f, 2.4022650696e-1f);
    p = fmaf(p, f, 6.9314718056e-1f);
    p = fmaf(p, f, 1.0f);
    int e = (int)r;
    return p * __int_as_float((e + 127) << 23);
}

__device__ __forceinline__ float gelu_f(float v) {
    return 0.5f * v * (1.0f + erff(v * 0.7071067811865476f));
}

__device__ __forceinline__ uint32_t f2tf(float x) {
    uint32_t r;
    asm("cvt.rna.tf32.f32 %0, %1;" : "=r"(r) : "f"(x));
    return r;
}

__device__ __forceinline__ uint32_t pkbf(float lo, float hi) {
    uint32_t r;
    asm("cvt.rn.bf16x2.f32 %0, %1, %2;" : "=r"(r) : "f"(hi), "f"(lo));
    return r;
}

__device__ __forceinline__ void mma_tf32(float c[4],
    uint32_t a0, uint32_t a1, uint32_t a2, uint32_t a3,
    uint32_t b0, uint32_t b1)
{
    asm volatile(
        "mma.sync.aligned.m16n8k8.row.col.f32.tf32.tf32.f32 "
        "{%0,%1,%2,%3}, {%4,%5,%6,%7}, {%8,%9}, {%0,%1,%2,%3};"
        : "+f"(c[0]), "+f"(c[1]), "+f"(c[2]), "+f"(c[3])
        : "r"(a0), "r"(a1), "r"(a2), "r"(a3), "r"(b0), "r"(b1));
}

__device__ __forceinline__ void mma_bf16(float c[4],
    uint32_t a0, uint32_t a1, uint32_t a2, uint32_t a3,
    uint32_t b0, uint32_t b1)
{
    asm volatile(
        "mma.sync.aligned.m16n8k16.row.col.f32.bf16.bf16.f32 "
        "{%0,%1,%2,%3}, {%4,%5,%6,%7}, {%8,%9}, {%0,%1,%2,%3};"
        : "+f"(c[0]), "+f"(c[1]), "+f"(c[2]), "+f"(c[3])
        : "r"(a0), "r"(a1), "r"(a2), "r"(a3), "r"(b0), "r"(b1));
}

__device__ __forceinline__ void cpa16(void* smem_dst, const void* gsrc) {
    uint32_t s = (uint32_t)__cvta_generic_to_shared(smem_dst);
    asm volatile("cp.async.cg.shared.global [%0], [%1], 16;" :: "r"(s), "l"(gsrc));
}

// ---------------- LayerNorm ----------------
__global__ void ln_kernel(const float* __restrict__ x, const float* __restrict__ gamma,
                          const float* __restrict__ beta, float* __restrict__ out) {
    int row = blockIdx.x;
    int t = threadIdx.x;
    float v = x[(size_t)row * DIM + t];
    float s = v, s2 = v * v;
    #pragma unroll
    for (int o = 16; o > 0; o >>= 1) {
        s  += __shfl_down_sync(0xffffffffu, s,  o);
        s2 += __shfl_down_sync(0xffffffffu, s2, o);
    }
    __shared__ float sh1[6], sh2[6];
    if ((t & 31) == 0) { sh1[t >> 5] = s; sh2[t >> 5] = s2; }
    __syncthreads();
    float ts = 0.f, ts2 = 0.f;
    #pragma unroll
    for (int i = 0; i < 6; i++) { ts += sh1[i]; ts2 += sh2[i]; }
    float mu  = ts * (1.0f / DIM);
    float var = ts2 * (1.0f / DIM) - mu * mu;
    float inv = rsqrtf(var + 1e-5f);
    out[(size_t)row * DIM + t] = (v - mu) * inv * gamma[t] + beta[t];
}

// ---------------- tensor-core GEMM: 128x64x16, 3-stage cp.async, bf16 mma ----------
// C = A(MxK)@B(KxN) [+bias][gelu|+D]; 256 threads, 32x32/warp via m16n8k16.bf16.
// f32 in smem; fragments packed to bf16x2 in-register at load (rn rounding).
template <int EPI>
__global__ void __launch_bounds__(256) tgemm_k(
    const float* __restrict__ A, const float* __restrict__ B,
    const float* __restrict__ bias, const float* __restrict__ D,
    float* __restrict__ C, int M, int N, int K, int ldc, int ldd,
    size_t sA, size_t sB, size_t sD, size_t sC)
{
    __shared__ float As[3][128][20];
    __shared__ float Bs[3][16][72];
    int tid = threadIdx.x;
    int row0 = blockIdx.y * 128, col0 = blockIdx.x * 64;
    int z = blockIdx.z;
    int warp = tid >> 5, lane = tid & 31;
    int wm = (warp >> 1) * 32, wn = (warp & 1) * 32;
    int grp = lane >> 2, qid = lane & 3;

    int ar = tid >> 2, aseg = (tid & 3) << 2;
    int br = tid >> 4, bseg = (tid & 15) << 2;

    const float* Ap = A + (size_t)z * sA + (size_t)row0 * K;
    const float* Bp = B + (size_t)z * sB + col0;
    const float* Dp = D + (size_t)z * sD;
    float*       Cp = C + (size_t)z * sC;

    float acc[2][4][4];
    #pragma unroll
    for (int i = 0; i < 2; i++)
        #pragma unroll
        for (int j = 0; j < 4; j++)
            #pragma unroll
            for (int r = 0; r < 4; r++) acc[i][j][r] = 0.f;

    int T = K >> 4;

    #define PREFETCH(k0, bufi) do { \
        cpa16(&As[bufi][ar][aseg],      Ap + (size_t)ar * K + (k0) + aseg); \
        cpa16(&As[bufi][ar + 64][aseg], Ap + (size_t)(ar + 64) * K + (k0) + aseg); \
        cpa16(&Bs[bufi][br][bseg],      Bp + (size_t)((k0) + br) * N + bseg); \
        asm volatile("cp.async.commit_group;"); } while (0)

    PREFETCH(0, 0);
    PREFETCH(16, 1);
    int kq = qid * 2;
    for (int t = 0; t < T; t++) {
        if (t + 1 < T) asm volatile("cp.async.wait_group 1;");
        else           asm volatile("cp.async.wait_group 0;");
        __syncthreads();
        if (t + 2 < T) PREFETCH((t + 2) << 4, (t + 2) % 3);
        int buf = t % 3;
        // single K=16 pass: bf16 m16n8k16
        uint32_t af[2][4], bf[4][2];
        #pragma unroll
        for (int i = 0; i < 2; i++) {
            int r = wm + i * 16 + grp;
            af[i][0] = pkbf(As[buf][r    ][kq    ], As[buf][r    ][kq + 1]);
            af[i][1] = pkbf(As[buf][r + 8][kq    ], As[buf][r + 8][kq + 1]);
            af[i][2] = pkbf(As[buf][r    ][kq + 8], As[buf][r    ][kq + 9]);
            af[i][3] = pkbf(As[buf][r + 8][kq + 8], As[buf][r + 8][kq + 9]);
        }
        #pragma unroll
        for (int j = 0; j < 4; j++) {
            int n0 = wn + j * 8 + grp;
            bf[j][0] = pkbf(Bs[buf][kq    ][n0], Bs[buf][kq + 1][n0]);
            bf[j][1] = pkbf(Bs[buf][kq + 8][n0], Bs[buf][kq + 9][n0]);
        }
        #pragma unroll
        for (int i = 0; i < 2; i++)
            #pragma unroll
            for (int j = 0; j < 4; j++)
                mma_bf16(acc[i][j], af[i][0], af[i][1], af[i][2], af[i][3],
                         bf[j][0], bf[j][1]);
        __syncthreads();
    }
    #undef PREFETCH

    #pragma unroll
    for (int i = 0; i < 2; i++) {
        #pragma unroll
        for (int hh = 0; hh < 2; hh++) {
            int r = row0 + wm + i * 16 + grp + hh * 8;
            #pragma unroll
            for (int j = 0; j < 4; j++) {
                int cl = col0 + wn + j * 8 + qid * 2;
                float v0 = acc[i][j][hh * 2 + 0];
                float v1 = acc[i][j][hh * 2 + 1];
                if (bias) { float2 bb = *(const float2*)(bias + cl); v0 += bb.x; v1 += bb.y; }
                if (EPI == 1) { v0 = gelu_f(v0); v1 = gelu_f(v1); }
                if (EPI == 2) {
                    float2 dd = *(const float2*)(Dp + (size_t)r * ldd + cl);
                    v0 += dd.x; v1 += dd.y;
                }
                float2 ov; ov.x = v0; ov.y = v1;
                *(float2*)(Cp + (size_t)r * ldc + cl) = ov;
            }
        }
    }
}

// ---------------- q projection ----------------
__global__ void qproj_kernel(const float* __restrict__ xn, const float* __restrict__ wq,
                             const float* __restrict__ bq, float* __restrict__ q) {
    int idx = blockIdx.x * 256 + threadIdx.x;
    if (idx >= TOT * RD) return;
    int tok = idx / RD, j = idx % RD;
    const float* xr = xn + (size_t)tok * DIM;
    float s0 = 0.f, s1 = 0.f, s2 = 0.f, s3 = 0.f;
    #pragma unroll 4
    for (int k = 0; k < DIM; k += 4) {
        s0 = fmaf(xr[k + 0], wq[(k + 0) * RD + j], s0);
        s1 = fmaf(xr[k + 1], wq[(k + 1) * RD + j], s1);
        s2 = fmaf(xr[k + 2], wq[(k + 2) * RD + j], s2);
        s3 = fmaf(xr[k + 3], wq[(k + 3) * RD + j], s3);
    }
    q[idx] = bq[j] + (s0 + s1) + (s2 + s3);
}

// ---------------- dictionary prep ----------------
__global__ void tdprep_kernel(const float* __restrict__ td,
                              const float* __restrict__ wk, const float* __restrict__ bk,
                              const float* __restrict__ wv, const float* __restrict__ bv,
                              const float* __restrict__ wtd, const float* __restrict__ btd,
                              float* __restrict__ kn, float* __restrict__ vout,
                              float* __restrict__ tdf) {
    int bm = blockIdx.x;
    int t = threadIdx.x;
    __shared__ float tr[DIM];
    __shared__ float kr[RD];
    __shared__ float sinv;
    tr[t] = td[(size_t)bm * DIM + t];
    __syncthreads();
    if (t < RD) {
        float s0 = 0.f, s1 = 0.f, s2 = 0.f, s3 = 0.f;
        #pragma unroll 4
        for (int k = 0; k < DIM; k += 4) {
            s0 = fmaf(tr[k + 0], wk[(k + 0) * RD + t], s0);
            s1 = fmaf(tr[k + 1], wk[(k + 1) * RD + t], s1);
            s2 = fmaf(tr[k + 2], wk[(k + 2) * RD + t], s2);
            s3 = fmaf(tr[k + 3], wk[(k + 3) * RD + t], s3);
        }
        kr[t] = bk[t] + (s0 + s1) + (s2 + s3);
    }
    {
        float s0 = 0.f, s1 = 0.f, s2 = 0.f, s3 = 0.f;
        #pragma unroll 4
        for (int k = 0; k < DIM; k += 4) {
            s0 = fmaf(tr[k + 0], wv[(k + 0) * DIM + t], s0);
            s1 = fmaf(tr[k + 1], wv[(k + 1) * DIM + t], s1);
            s2 = fmaf(tr[k + 2], wv[(k + 2) * DIM + t], s2);
            s3 = fmaf(tr[k + 3], wv[(k + 3) * DIM + t], s3);
        }
        vout[(size_t)bm * DIM + t] = bv[t] + (s0 + s1) + (s2 + s3);
    }
    if (t < DTD) {
        float s0 = 0.f, s1 = 0.f, s2 = 0.f, s3 = 0.f;
        #pragma unroll 4
        for (int k = 0; k < DIM; k += 4) {
            s0 = fmaf(tr[k + 0], wtd[(k + 0) * DTD + t], s0);
            s1 = fmaf(tr[k + 1], wtd[(k + 1) * DTD + t], s1);
            s2 = fmaf(tr[k + 2], wtd[(k + 2) * DTD + t], s2);
            s3 = fmaf(tr[k + 3], wtd[(k + 3) * DTD + t], s3);
        }
        tdf[(size_t)bm * DTD + t] = btd[t] + (s0 + s1) + (s2 + s3);
    }
    __syncthreads();
    if (t == 0) {
        float n = 0.f;
        for (int i = 0; i < RD; i++) n += kr[i] * kr[i];
        sinv = 1.0f / fmaxf(sqrtf(n), 1e-12f);
    }
    __syncthreads();
    if (t < RD) kn[bm * RD + t] = kr[t] * sinv;
}

// ---------------- ATD cross-attn ----------------
__global__ void atd_kernel(const float* __restrict__ q, const float* __restrict__ kn,
                           const float* __restrict__ scale_p,
                           float* __restrict__ sim, int* __restrict__ tkid) {
    int tok = blockIdx.x;
    int b = tok >> 14;
    int t = threadIdx.x;
    int w = t >> 5, lane = t & 31;
    __shared__ float qn[RD];
    __shared__ float wmax[2]; __shared__ int widx[2];
    __shared__ float wsum[2];
    __shared__ float red0, red1;
    if (t == 0) {
        float qq[RD]; float n = 0.f;
        #pragma unroll
        for (int i = 0; i < RD; i++) { qq[i] = q[(size_t)tok * RD + i]; n += qq[i] * qq[i]; }
        float inv = 1.0f / fmaxf(sqrtf(n), 1e-12f);
        #pragma unroll
        for (int i = 0; i < RD; i++) qn[i] = qq[i] * inv;
    }
    __syncthreads();
    float sc = 1.0f + fminf(fmaxf(scale_p[0], 0.0f), 3.0f) * 4.1588830833596715f;
    const float* kr = kn + ((size_t)b * NDICT + t) * RD;
    float s = 0.f;
    #pragma unroll
    for (int i = 0; i < RD; i++) s = fmaf(qn[i], kr[i], s);
    float sv = s * sc;

    float mv = sv; int mi = t;
    #pragma unroll
    for (int o = 16; o > 0; o >>= 1) {
        float ov = __shfl_down_sync(0xffffffffu, mv, o);
        int   oi = __shfl_down_sync(0xffffffffu, mi, o);
        if (ov > mv || (ov == mv && oi < mi)) { mv = ov; mi = oi; }
    }
    if (lane == 0) { wmax[w] = mv; widx[w] = mi; }
    __syncthreads();
    if (t == 0) {
        float m0 = wmax[0], m1 = wmax[1];
        int am = (m1 > m0) ? widx[1] : widx[0];
        red0 = fmaxf(m0, m1);
        tkid[tok] = am;
    }
    __syncthreads();
    float e = fexp(sv - red0);
    float es = e;
    #pragma unroll
    for (int o = 16; o > 0; o >>= 1) es += __shfl_down_sync(0xffffffffu, es, o);
    if (lane == 0) wsum[w] = es;
    __syncthreads();
    if (t == 0) red1 = 1.0f / (wsum[0] + wsum[1]);
    __syncthreads();
    sim[(size_t)tok * NDICT + t] = e * red1;
}

// ---------------- stable counting sort ----------------
__global__ void hist_kernel(const int* __restrict__ tkid, int* __restrict__ off) {
    int b = blockIdx.x;
    __shared__ int h[NDICT];
    int t = threadIdx.x;
    if (t < NDICT) h[t] = 0;
    __syncthreads();
    for (int i = t; i < NTOKS; i += 256) atomicAdd(&h[tkid[b * NTOKS + i]], 1);
    __syncthreads();
    if (t == 0) {
        int acc = 0;
        for (int k = 0; k < NDICT; k++) { off[b * NDICT + k] = acc; acc += h[k]; }
    }
}

__global__ void scatter_kernel(const int* __restrict__ tkid, const int* __restrict__ off,
                               int* __restrict__ sidx) {
    int b = blockIdx.x >> 6, key = blockIdx.x & 63;
    const int* ids = tkid + b * NTOKS;
    int base = off[b * NDICT + key];
    int t = threadIdx.x, lane = t & 31, w = t >> 5;
    __shared__ int wc[8];
    for (int c = 0; c < NTOKS; c += 256) {
        int id = ids[c + t];
        bool f = (id == key);
        unsigned m = __ballot_sync(0xffffffffu, f);
        if (lane == 0) wc[w] = __popc(m);
        __syncthreads();
        int pre = 0, tot = 0;
        #pragma unroll
        for (int i = 0; i < 8; i++) { int cnt = wc[i]; tot += cnt; if (i < w) pre += cnt; }
        if (f) sidx[b * NTOKS + base + pre + __popc(m & ((1u << lane) - 1))] = c + t;
        base += tot;
        __syncthreads();
    }
}

// ---------------- AC_MSA via tensor-core MMA ----------------
__global__ void __launch_bounds__(256) acmsa_mma_kernel(
    const float* __restrict__ qkv, const int* __restrict__ sidx,
    float* __restrict__ ycat)
{
    __shared__ __align__(16) char smem_raw[27136];
    float* sQ = (float*)smem_raw;
    float* sK = (float*)smem_raw;
    __nv_bfloat16* sVT = (__nv_bfloat16*)(smem_raw + 18432);
    uint32_t* vtw = (uint32_t*)(smem_raw + 18432);

    int g = blockIdx.x, head = blockIdx.y, b = blockIdx.z;
    int tid = threadIdx.x;
    int warp = tid >> 5, lane = tid & 31;
    int grp = lane >> 2, qid = lane & 3;
    int q0 = warp * 16;
    const int* sp = sidx + b * NTOKS + g * GS;

    {
        int r = tid >> 1, off = (tid & 1) * 16;
        int tok = sp[r];
        const float4* src = (const float4*)(qkv + ((size_t)(b * NTOKS + tok)) * H3
                                            + head * HD + off);
        #pragma unroll
        for (int u = 0; u < 4; u++) {
            float4 v = src[u];
            float* d = sQ + r * 36 + off + u * 4;
            d[0] = v.x * 0.17677669529663687f;
            d[1] = v.y * 0.17677669529663687f;
            d[2] = v.z * 0.17677669529663687f;
            d[3] = v.w * 0.17677669529663687f;
        }
    }
    __syncthreads();

    uint32_t qa[4][4];
    #pragma unroll
    for (int ks = 0; ks < 4; ks++) {
        qa[ks][0] = f2tf(sQ[(q0 + grp    ) * 36 + ks * 8 + qid    ]);
        qa[ks][1] = f2tf(sQ[(q0 + grp + 8) * 36 + ks * 8 + qid    ]);
        qa[ks][2] = f2tf(sQ[(q0 + grp    ) * 36 + ks * 8 + qid + 4]);
        qa[ks][3] = f2tf(sQ[(q0 + grp + 8) * 36 + ks * 8 + qid + 4]);
    }
    int tok0 = sp[q0 + grp], tok1 = sp[q0 + grp + 8];

    float o[4][4];
    #pragma unroll
    for (int nt = 0; nt < 4; nt++)
        #pragma unroll
        for (int r = 0; r < 4; r++) o[nt][r] = 0.f;
    float m0v = -1e30f, m1v = -1e30f, l0 = 0.f, l1 = 0.f;
    __syncthreads();

    {
        int key = tid >> 1, part = tid & 1;
        int tok = sp[key];
        const float* basep = qkv + ((size_t)(b * NTOKS + tok)) * H3 + head * HD;
        const float4* ksrc = (const float4*)(basep + DIM + part * 16);
        float* kd = sK + key * 36 + part * 16;
        #pragma unroll
        for (int u = 0; u < 4; u++) {
            float4 kv = ksrc[u];
            kd[u * 4 + 0] = kv.x; kd[u * 4 + 1] = kv.y;
            kd[u * 4 + 2] = kv.z; kd[u * 4 + 3] = kv.w;
        }
        const float4* vsrc = (const float4*)(basep + 2 * DIM + part * 16);
        int d0 = part * 16;
        #pragma unroll
        for (int u = 0; u < 4; u++) {
            float4 vv = vsrc[u];
            sVT[(d0 + u * 4 + 0) * 136 + key] = __float2bfloat16(vv.x);
            sVT[(d0 + u * 4 + 1) * 136 + key] = __float2bfloat16(vv.y);
            sVT[(d0 + u * 4 + 2) * 136 + key] = __float2bfloat16(vv.z);
            sVT[(d0 + u * 4 + 3) * 136 + key] = __float2bfloat16(vv.w);
        }
    }
    __syncthreads();

    for (int kc = 0; kc < 4; kc++) {
        float s[4][4];
        #pragma unroll
        for (int nt = 0; nt < 4; nt++)
            #pragma unroll
            for (int r = 0; r < 4; r++) s[nt][r] = 0.f;
        #pragma unroll
        for (int nt = 0; nt < 4; nt++) {
            int krow = (kc * 32 + nt * 8 + grp) * 36;
            #pragma unroll
            for (int ks = 0; ks < 4; ks++) {
                uint32_t b0 = f2tf(sK[krow + ks * 8 + qid]);
                uint32_t b1 = f2tf(sK[krow + ks * 8 + qid + 4]);
                mma_tf32(s[nt], qa[ks][0], qa[ks][1], qa[ks][2], qa[ks][3], b0, b1);
            }
        }
        float mx0 = fmaxf(fmaxf(s[0][0], s[0][1]), fmaxf(s[1][0], s[1][1]));
        mx0 = fmaxf(mx0, fmaxf(fmaxf(s[2][0], s[2][1]), fmaxf(s[3][0], s[3][1])));
        float mx1 = fmaxf(fmaxf(s[0][2], s[0][3]), fmaxf(s[1][2], s[1][3]));
        mx1 = fmaxf(mx1, fmaxf(fmaxf(s[2][2], s[2][3]), fmaxf(s[3][2], s[3][3])));
        mx0 = fmaxf(mx0, __shfl_xor_sync(0xffffffffu, mx0, 1));
        mx0 = fmaxf(mx0, __shfl_xor_sync(0xffffffffu, mx0, 2));
        mx1 = fmaxf(mx1, __shfl_xor_sync(0xffffffffu, mx1, 1));
        mx1 = fmaxf(mx1, __shfl_xor_sync(0xffffffffu, mx1, 2));
        float mn0 = fmaxf(m0v, mx0), mn1 = fmaxf(m1v, mx1);
        float f0 = fexp(m0v - mn0), f1 = fexp(m1v - mn1);
        m0v = mn0; m1v = mn1;
        l0 *= f0; l1 *= f1;
        #pragma unroll
        for (int nt = 0; nt < 4; nt++) {
            o[nt][0] *= f0; o[nt][1] *= f0;
            o[nt][2] *= f1; o[nt][3] *= f1;
        }
        float ps0 = 0.f, ps1 = 0.f;
        #pragma unroll
        for (int nt = 0; nt < 4; nt++) {
            s[nt][0] = fexp(s[nt][0] - mn0); ps0 += s[nt][0];
            s[nt][1] = fexp(s[nt][1] - mn0); ps0 += s[nt][1];
            s[nt][2] = fexp(s[nt][2] - mn1); ps1 += s[nt][2];
            s[nt][3] = fexp(s[nt][3] - mn1); ps1 += s[nt][3];
        }
        l0 += ps0; l1 += ps1;
        #pragma unroll
        for (int ks = 0; ks < 2; ks++) {
            uint32_t a0 = pkbf(s[2 * ks][0],     s[2 * ks][1]);
            uint32_t a1 = pkbf(s[2 * ks][2],     s[2 * ks][3]);
            uint32_t a2 = pkbf(s[2 * ks + 1][0], s[2 * ks + 1][1]);
            uint32_t a3 = pkbf(s[2 * ks + 1][2], s[2 * ks + 1][3]);
            #pragma unroll
            for (int ntd = 0; ntd < 4; ntd++) {
                int base = (ntd * 8 + grp) * 68 + kc * 16 + ks * 8 + qid;
                mma_bf16(o[ntd], a0, a1, a2, a3, vtw[base], vtw[base + 4]);
            }
        }
    }
    l0 += __shfl_xor_sync(0xffffffffu, l0, 1);
    l0 += __shfl_xor_sync(0xffffffffu, l0, 2);
    l1 += __shfl_xor_sync(0xffffffffu, l1, 1);
    l1 += __shfl_xor_sync(0xffffffffu, l1, 2);
    float inv0 = 1.0f / l0, inv1 = 1.0f / l1;
    float* out0 = ycat + ((size_t)(b * NTOKS + tok0)) * YC + DIM + head * HD;
    float* out1 = ycat + ((size_t)(b * NTOKS + tok1)) * YC + DIM + head * HD;
    #pragma unroll
    for (int nt = 0; nt < 4; nt++) {
        float2 w0; w0.x = o[nt][0] * inv0; w0.y = o[nt][1] * inv0;
        float2 w1; w1.x = o[nt][2] * inv1; w1.y = o[nt][3] * inv1;
        *(float2*)(out0 + nt * 8 + 2 * qid) = w0;
        *(float2*)(out1 + nt * 8 + 2 * qid) = w1;
    }
}

// ---------------- transposed relative position bias ----------------
__global__ void rpbt_kernel(const int* __restrict__ rpi, const float* __restrict__ table,
                            float* __restrict__ rpbT) {
    int idx = blockIdx.x * 256 + threadIdx.x;
    if (idx >= NHEAD * WIN * WIN) return;
    int h = idx >> 16;
    int r = idx & 65535;
    int kj = r >> 8, qi = r & 255;
    rpbT[idx] = table[rpi[qi * WIN + kj] * NHEAD + h];
}

// ---------------- shifted-window attention via MMA ----------------
__global__ void __launch_bounds__(512) winattn_mma_kernel(
    const float* __restrict__ qkv, const float* __restrict__ mask,
    const float* __restrict__ rpbT, float* __restrict__ ycat)
{
    __shared__ __align__(16) char smem_raw[36864];
    float* sQ = (float*)smem_raw;
    float* sK = (float*)smem_raw;
    __nv_bfloat16* sVT = (__nv_bfloat16*)(smem_raw + 18432);
    uint32_t* vtw = (uint32_t*)(smem_raw + 18432);

    int wl = blockIdx.x, head = blockIdx.y, b = blockIdx.z;
    int wy = wl >> 3, wx = wl & 7;
    int tid = threadIdx.x;
    int warp = tid >> 5, lane = tid & 31;
    int grp = lane >> 2, qid = lane & 3;
    int q0 = warp * 16;

    {
        int r = tid >> 1, off = (tid & 1) * 16;
        int i = r >> 4, j = r & 15;
        int n = (((wy * WS + i + SS) & 127) << 7) | ((wx * WS + j + SS) & 127);
        const float4* src = (const float4*)(qkv + ((size_t)(b * NTOKS + n)) * H3
                                            + head * HD + off);
        #pragma unroll
        for (int u = 0; u < 4; u++) {
            float4 v = src[u];
            float* d = sQ + r * 36 + off + u * 4;
            d[0] = v.x * 0.17677669529663687f;
            d[1] = v.y * 0.17677669529663687f;
            d[2] = v.z * 0.17677669529663687f;
            d[3] = v.w * 0.17677669529663687f;
        }
    }
    __syncthreads();

    uint32_t qa[4][4];
    #pragma unroll
    for (int ks = 0; ks < 4; ks++) {
        qa[ks][0] = f2tf(sQ[(q0 + grp    ) * 36 + ks * 8 + qid    ]);
        qa[ks][1] = f2tf(sQ[(q0 + grp + 8) * 36 + ks * 8 + qid    ]);
        qa[ks][2] = f2tf(sQ[(q0 + grp    ) * 36 + ks * 8 + qid + 4]);
        qa[ks][3] = f2tf(sQ[(q0 + grp + 8) * 36 + ks * 8 + qid + 4]);
    }
    int r0 = q0 + grp, r1 = r0 + 8;
    int i0 = r0 >> 4, j0 = r0 & 15;
    int i1 = r1 >> 4, j1 = r1 & 15;
    int tok0 = (((wy * WS + i0 + SS) & 127) << 7) | ((wx * WS + j0 + SS) & 127);
    int tok1 = (((wy * WS + i1 + SS) & 127) << 7) | ((wx * WS + j1 + SS) & 127);
    const float* rpbh  = rpbT + (size_t)head * (WIN * WIN);
    const float* maskw = mask + (size_t)wl * (WIN * WIN);

    float o[4][4];
    #pragma unroll
    for (int nt = 0; nt < 4; nt++)
        #pragma unroll
        for (int r = 0; r < 4; r++) o[nt][r] = 0.f;
    float m0v = -1e30f, m1v = -1e30f, l0 = 0.f, l1 = 0.f;
    __syncthreads();

    for (int kt = 0; kt < 2; kt++) {
        {
            int key = tid >> 2, part = tid & 3;
            int p = kt * 128 + key;
            int pi = p >> 4, pj = p & 15;
            int np = (((wy * WS + pi + SS) & 127) << 7) | ((wx * WS + pj + SS) & 127);
            const float* basep = qkv + ((size_t)(b * NTOKS + np)) * H3 + head * HD;
            const float4* ksrc = (const float4*)(basep + DIM + part * 8);
            float4 k0 = ksrc[0], k1 = ksrc[1];
            float* kd = sK + key * 36 + part * 8;
            kd[0] = k0.x; kd[1] = k0.y; kd[2] = k0.z; kd[3] = k0.w;
            kd[4] = k1.x; kd[5] = k1.y; kd[6] = k1.z; kd[7] = k1.w;
            const float4* vsrc = (const float4*)(basep + 2 * DIM + part * 8);
            float4 v0 = vsrc[0], v1 = vsrc[1];
            int d0 = part * 8;
            sVT[(d0 + 0) * 136 + key] = __float2bfloat16(v0.x);
            sVT[(d0 + 1) * 136 + key] = __float2bfloat16(v0.y);
            sVT[(d0 + 2) * 136 + key] = __float2bfloat16(v0.z);
            sVT[(d0 + 3) * 136 + key] = __float2bfloat16(v0.w);
            sVT[(d0 + 4) * 136 + key] = __float2bfloat16(v1.x);
            sVT[(d0 + 5) * 136 + key] = __float2bfloat16(v1.y);
            sVT[(d0 + 6) * 136 + key] = __float2bfloat16(v1.z);
            sVT[(d0 + 7) * 136 + key] = __float2bfloat16(v1.w);
        }
        __syncthreads();

        for (int kc = 0; kc < 4; kc++) {
            int kbase = kt * 128 + kc * 32;
            float s[4][4];
            #pragma unroll
            for (int nt = 0; nt < 4; nt++)
                #pragma unroll
                for (int r = 0; r < 4; r++) s[nt][r] = 0.f;
            #pragma unroll
            for (int nt = 0; nt < 4; nt++) {
                int krow = (kc * 32 + nt * 8 + grp) * 36;
                #pragma unroll
                for (int ks = 0; ks < 4; ks++) {
                    uint32_t b0 = f2tf(sK[krow + ks * 8 + qid]);
                    uint32_t b1 = f2tf(sK[krow + ks * 8 + qid + 4]);
                    mma_tf32(s[nt], qa[ks][0], qa[ks][1], qa[ks][2], qa[ks][3], b0, b1);
                }
            }
            #pragma unroll
            for (int nt = 0; nt < 4; nt++) {
                int c0 = kbase + nt * 8 + 2 * qid;
                s[nt][0] += rpbh[c0 * WIN + r0] + maskw[c0 * WIN + r0];
                s[nt][1] += rpbh[(c0 + 1) * WIN + r0] + maskw[(c0 + 1) * WIN + r0];
                s[nt][2] += rpbh[c0 * WIN + r1] + maskw[c0 * WIN + r1];
                s[nt][3] += rpbh[(c0 + 1) * WIN + r1] + maskw[(c0 + 1) * WIN + r1];
            }
            float mx0 = fmaxf(fmaxf(s[0][0], s[0][1]), fmaxf(s[1][0], s[1][1]));
            mx0 = fmaxf(mx0, fmaxf(fmaxf(s[2][0], s[2][1]), fmaxf(s[3][0], s[3][1])));
            float mx1 = fmaxf(fmaxf(s[0][2], s[0][3]), fmaxf(s[1][2], s[1][3]));
            mx1 = fmaxf(mx1, fmaxf(fmaxf(s[2][2], s[2][3]), fmaxf(s[3][2], s[3][3])));
            mx0 = fmaxf(mx0, __shfl_xor_sync(0xffffffffu, mx0, 1));
            mx0 = fmaxf(mx0, __shfl_xor_sync(0xffffffffu, mx0, 2));
            mx1 = fmaxf(mx1, __shfl_xor_sync(0xffffffffu, mx1, 1));
            mx1 = fmaxf(mx1, __shfl_xor_sync(0xffffffffu, mx1, 2));
            float mn0 = fmaxf(m0v, mx0), mn1 = fmaxf(m1v, mx1);
            float f0 = fexp(m0v - mn0), f1 = fexp(m1v - mn1);
            m0v = mn0; m1v = mn1;
            l0 *= f0; l1 *= f1;
            #pragma unroll
            for (int nt = 0; nt < 4; nt++) {
                o[nt][0] *= f0; o[nt][1] *= f0;
                o[nt][2] *= f1; o[nt][3] *= f1;
            }
            float ps0 = 0.f, ps1 = 0.f;
            #pragma unroll
            for (int nt = 0; nt < 4; nt++) {
                s[nt][0] = fexp(s[nt][0] - mn0); ps0 += s[nt][0];
                s[nt][1] = fexp(s[nt][1] - mn0); ps0 += s[nt][1];
                s[nt][2] = fexp(s[nt][2] - mn1); ps1 += s[nt][2];
                s[nt][3] = fexp(s[nt][3] - mn1); ps1 += s[nt][3];
            }
            l0 += ps0; l1 += ps1;
            #pragma unroll
            for (int ks = 0; ks < 2; ks++) {
                uint32_t a0 = pkbf(s[2 * ks][0],     s[2 * ks][1]);
                uint32_t a1 = pkbf(s[2 * ks][2],     s[2 * ks][3]);
                uint32_t a2 = pkbf(s[2 * ks + 1][0], s[2 * ks + 1][1]);
                uint32_t a3 = pkbf(s[2 * ks + 1][2], s[2 * ks + 1][3]);
                #pragma unroll
                for (int ntd = 0; ntd < 4; ntd++) {
                    int base = (ntd * 8 + grp) * 68 + kc * 16 + ks * 8 + qid;
                    mma_bf16(o[ntd], a0, a1, a2, a3, vtw[base], vtw[base + 4]);
                }
            }
        }
        __syncthreads();
    }
    l0 += __shfl_xor_sync(0xffffffffu, l0, 1);
    l0 += __shfl_xor_sync(0xffffffffu, l0, 2);
    l1 += __shfl_xor_sync(0xffffffffu, l1, 1);
    l1 += __shfl_xor_sync(0xffffffffu, l1, 2);
    float inv0 = 1.0f / l0, inv1 = 1.0f / l1;
    float* out0 = ycat + ((size_t)(b * NTOKS + tok0)) * YC + head * HD;
    float* out1 = ycat + ((size_t)(b * NTOKS + tok1)) * YC + head * HD;
    #pragma unroll
    for (int nt = 0; nt < 4; nt++) {
        float2 w0; w0.x = o[nt][0] * inv0; w0.y = o[nt][1] * inv0;
        float2 w1; w1.x = o[nt][2] * inv1; w1.y = o[nt][3] * inv1;
        *(float2*)(out0 + nt * 8 + 2 * qid) = w0;
        *(float2*)(out1 + nt * 8 + 2 * qid) = w1;
    }
}

// ---------------- pack merged projection ----------------
__global__ void packproj_kernel(const float* __restrict__ ww, const float* __restrict__ wa,
                                const float* __restrict__ bw, const float* __restrict__ ba,
                                float* __restrict__ Bcat, float* __restrict__ bcat) {
    int idx = blockIdx.x * 256 + threadIdx.x;
    if (idx >= YC * DIM) return;
    int k = idx / DIM, n = idx % DIM;
    Bcat[idx] = (k < DIM) ? ww[k * DIM + n] : wa[(k - DIM) * DIM + n];
    if (idx < DIM) bcat[idx] = bw[idx] + ba[idx];
}

// ---------------- gather token-dict features ----------------
__global__ void gather_td_kernel(const float* __restrict__ tdf, const int* __restrict__ tkid,
                                 float* __restrict__ xc) {
    int idx = blockIdx.x * 256 + threadIdx.x;
    if (idx >= TOT * DTD) return;
    int tok = idx >> 6, j = idx & 63;
    int b = tok >> 14;
    xc[(size_t)tok * CH + MLPH + j] = tdf[((size_t)b * NDICT + tkid[tok]) * DTD + j];
}

// ---------------- depthwise 5x5 conv ----------------
__global__ void dwconv_kernel(const float* __restrict__ xc, const float* __restrict__ w,
                              const float* __restrict__ bias, float* __restrict__ sout) {
    int u = blockIdx.x * 256 + threadIdx.x;
    if (u >= TOT * CH / 4) return;
    int c = u % CH;
    int p4 = u / CH;
    int x = p4 & 127, y4 = (p4 >> 7) & 31, b = p4 >> 12;
    int y0 = y4 << 2;
    float wr[25];
    #pragma unroll
    for (int i = 0; i < 25; i++) wr[i] = w[i * CH + c];
    float acc[4] = {0.f, 0.f, 0.f, 0.f};
    #pragma unroll
    for (int ry = 0; ry < 8; ry++) {
        int yy = y0 + ry - 2;
        if ((unsigned)yy >= 128u) continue;
        #pragma unroll
        for (int dx = 0; dx < 5; dx++) {
            int xx = x + dx - 2;
            if ((unsigned)xx >= 128u) continue;
            float v = xc[(size_t)((b << 14) | (yy << 7) | xx) * CH + c];
            #pragma unroll
            for (int r = 0; r < 4; r++) {
                int dy = ry - r;
                if (dy >= 0 && dy < 5)
                    acc[r] = fmaf(v, wr[dy * 5 + dx], acc[r]);
            }
        }
    }
    float bc = bias[c];
    #pragma unroll
    for (int r = 0; r < 4; r++) {
        size_t idx = (size_t)((b << 14) | ((y0 + r) << 7) | x) * CH + c;
        sout[idx] = xc[idx] + gelu_f(acc[r] + bc);
    }
}

// ---------------- host side ----------------
static void sgemm(int epi, const float* A, const float* B, const float* bias, const float* D,
                  float* C, int M, int N, int K, int ldc, int ldd,
                  int nz = 1, size_t sA = 0, size_t sB = 0, size_t sD = 0, size_t sC = 0) {
    dim3 grid(N / 64, M / 128, nz), block(256);
    if (epi == 0)      tgemm_k<0><<<grid, block>>>(A, B, bias, D, C, M, N, K, ldc, ldd, sA, sB, sD, sC);
    else if (epi == 1) tgemm_k<1><<<grid, block>>>(A, B, bias, D, C, M, N, K, ldc, ldd, sA, sB, sD, sC);
    else               tgemm_k<2><<<grid, block>>>(A, B, bias, D, C, M, N, K, ldc, ldd, sA, sB, sD, sC);
}

extern "C" void kernel_launch(void* const* d_in, const int* in_sizes, int n_in,
                              void* d_out, int out_size) {
    (void)in_sizes; (void)out_size;
    const float* x         = (const float*)d_in[0];
    const float* td        = (const float*)d_in[1];
    const float* attn_mask = (const float*)d_in[2];
    const int*   rpi       = (const int*)  d_in[3];
    int base = (n_in >= 32) ? 6 : 4;
    const float* norm1_g    = (const float*)d_in[base + 0];
    const float* norm1_b    = (const float*)d_in[base + 1];
    const float* norm2_g    = (const float*)d_in[base + 2];
    const float* norm2_b    = (const float*)d_in[base + 3];
    const float* wqkv_w     = (const float*)d_in[base + 4];
    const float* wqkv_b     = (const float*)d_in[base + 5];
    const float* wq_w       = (const float*)d_in[base + 6];
    const float* wq_b       = (const float*)d_in[base + 7];
    const float* wk_w       = (const float*)d_in[base + 8];
    const float* wk_b       = (const float*)d_in[base + 9];
    const float* wv_w       = (const float*)d_in[base + 10];
    const float* wv_b       = (const float*)d_in[base + 11];
    const float* atd_scale  = (const float*)d_in[base + 12];
    const float* aca_proj_w = (const float*)d_in[base + 13];
    const float* aca_proj_b = (const float*)d_in[base + 14];
    const float* rpb_table  = (const float*)d_in[base + 15];
    const float* win_proj_w = (const float*)d_in[base + 16];
    const float* win_proj_b = (const float*)d_in[base + 17];
    const float* fc_td_w    = (const float*)d_in[base + 18];
    const float* fc_td_b    = (const float*)d_in[base + 19];
    const float* fc1_w      = (const float*)d_in[base + 20];
    const float* fc1_b      = (const float*)d_in[base + 21];
    const float* dw_w       = (const float*)d_in[base + 22];
    const float* dw_b       = (const float*)d_in[base + 23];
    const float* fc2_w      = (const float*)d_in[base + 24];
    const float* fc2_b      = (const float*)d_in[base + 25];

    float *xn, *qkv, *qb, *kn, *vb, *tdf, *sim, *ycat, *xs, *rpbT, *xc, *sb, *bcat, *bcatb;
    int *tkid, *sidx, *off;
    cudaGetSymbolAddress((void**)&xn,    g_xn);
    cudaGetSymbolAddress((void**)&qkv,   g_qkv);
    cudaGetSymbolAddress((void**)&qb,    g_q);
    cudaGetSymbolAddress((void**)&kn,    g_kn);
    cudaGetSymbolAddress((void**)&vb,    g_v);
    cudaGetSymbolAddress((void**)&tdf,   g_tdf);
    cudaGetSymbolAddress((void**)&sim,   g_sim);
    cudaGetSymbolAddress((void**)&tkid,  g_tkid);
    cudaGetSymbolAddress((void**)&sidx,  g_sidx);
    cudaGetSymbolAddress((void**)&off,   g_off);
    cudaGetSymbolAddress((void**)&ycat,  g_ycat);
    cudaGetSymbolAddress((void**)&xs,    g_xs);
    cudaGetSymbolAddress((void**)&rpbT,  g_rpbT);
    cudaGetSymbolAddress((void**)&xc,    g_xc);
    cudaGetSymbolAddress((void**)&sb,    g_s);
    cudaGetSymbolAddress((void**)&bcat,  g_bcat);
    cudaGetSymbolAddress((void**)&bcatb, g_bcatb);

    bool fork = (g_s2 != nullptr && g_ev1 != nullptr && g_ev2 != nullptr);

    // 1) LN1 + qkv GEMM on main stream
    ln_kernel<<<TOT, DIM>>>(x, norm1_g, norm1_b, xn);
    sgemm(0, xn, wqkv_w, wqkv_b, nullptr, qkv, TOT, H3, DIM, H3, 0);

    if (fork) {
        // fork: side stream does packproj + rpbt + winattn (needs only qkv)
        cudaEventRecord(g_ev1, 0);
        cudaStreamWaitEvent(g_s2, g_ev1, 0);
        packproj_kernel<<<(YC * DIM + 255) / 256, 256, 0, g_s2>>>(
            win_proj_w, aca_proj_w, win_proj_b, aca_proj_b, bcat, bcatb);
        rpbt_kernel<<<(NHEAD * WIN * WIN + 255) / 256, 256, 0, g_s2>>>(rpi, rpb_table, rpbT);
        winattn_mma_kernel<<<dim3(NWIN, NHEAD, BATCH), 512, 0, g_s2>>>(
            qkv, attn_mask, rpbT, ycat);
        cudaEventRecord(g_ev2, g_s2);
    }

    // main stream: ATD chain
    qproj_kernel<<<(TOT * RD + 255) / 256, 256>>>(xn, wq_w, wq_b, qb);
    tdprep_kernel<<<BATCH * NDICT, DIM>>>(td, wk_w, wk_b, wv_w, wv_b, fc_td_w, fc_td_b,
                                          kn, vb, tdf);
    atd_kernel<<<TOT, NDICT>>>(qb, kn, atd_scale, sim, tkid);
    sgemm(2, sim, vb, nullptr, x, xs, NTOKS, DIM, NDICT, DIM, DIM,
          BATCH, (size_t)NTOKS * NDICT, (size_t)NDICT * DIM,
          (size_t)NTOKS * DIM, (size_t)NTOKS * DIM);
    hist_kernel<<<BATCH, 256>>>(tkid, off);
    scatter_kernel<<<BATCH * NDICT, 256>>>(tkid, off, sidx);
    acmsa_mma_kernel<<<dim3(NG, NHEAD, BATCH), 256>>>(qkv, sidx, ycat);

    if (fork) {
        cudaStreamWaitEvent(0, g_ev2, 0);   // join
    } else {
        packproj_kernel<<<(YC * DIM + 255) / 256, 256>>>(win_proj_w, aca_proj_w,
                                                         win_proj_b, aca_proj_b, bcat, bcatb);
        rpbt_kernel<<<(NHEAD * WIN * WIN + 255) / 256, 256>>>(rpi, rpb_table, rpbT);
        winattn_mma_kernel<<<dim3(NWIN, NHEAD, BATCH), 512>>>(qkv, attn_mask, rpbT, ycat);
    }

    // merged projection + FFN tail
    sgemm(2, ycat, bcat, bcatb, xs, xs, TOT, DIM, YC, DIM, DIM);
    ln_kernel<<<TOT, DIM>>>(xs, norm2_g, norm2_b, xn);
    sgemm(1, xn, fc1_w, fc1_b, nullptr, xc, TOT, MLPH, DIM, CH, 0);
    gather_td_kernel<<<(TOT * DTD + 255) / 256, 256>>>(tdf, tkid, xc);
    dwconv_kernel<<<(TOT * CH / 4 + 255) / 256, 256>>>(xc, dw_w, dw_b, sb);
    sgemm(2, sb, fc2_w, fc2_b, xs, (float*)d_out, TOT, DIM, CH, DIM, DIM);
}

// round 14
// speedup vs baseline: 1.1054x; 1.1054x over previous
#include <cuda_runtime.h>
#include <cuda_bf16.h>
#include <cstdint>
#include <math.h>

// ---------------- problem constants ----------------
#define BATCH 4
#define IMGH 128
#define IMGW 128
#define NTOKS (IMGH*IMGW)
#define TOT (BATCH*NTOKS)
#define DIM 192
#define H3 576
#define NHEAD 6
#define HD 32
#define WS 16
#define SS 8
#define NWIN 64
#define WIN 256
#define NDICT 64
#define RD 10
#define DTD 64
#define MLPH 384
#define CH 448
#define GS 128
#define NG 128
#define YC 384

// ---------------- scratch ----------------
__device__ __align__(16) float g_xn  [TOT*DIM];
__device__ __align__(16) float g_qkv [TOT*H3];
__device__ __align__(16) float g_q   [TOT*RD];
__device__ __align__(16) float g_kn  [BATCH*NDICT*RD];
__device__ __align__(16) float g_v   [BATCH*NDICT*DIM];
__device__ __align__(16) float g_tdf [BATCH*NDICT*DTD];
__device__ __align__(16) float g_sim [TOT*NDICT];
__device__           int   g_tkid[TOT];
__device__           int   g_sidx[TOT];
__device__           int   g_off [BATCH*NDICT];
__device__ __align__(16) float g_ycat[TOT*YC];
__device__ __align__(16) float g_xs  [TOT*DIM];
__device__ __align__(16) float g_rpbT[NHEAD*WIN*WIN];
__device__ __align__(16) float g_xc  [TOT*CH];
__device__ __align__(16) float g_s   [TOT*CH];
__device__ __align__(16) float g_bcat[YC*DIM];
__device__ __align__(16) float g_bcatb[DIM];

// ---------------- side stream for fork/join (created at static init) ----------------
static cudaStream_t g_s2 = nullptr;
static cudaEvent_t g_ev1 = nullptr, g_ev2 = nullptr;
namespace {
struct StreamInit {
    StreamInit() {
        if (cudaStreamCreateWithFlags(&g_s2, cudaStreamNonBlocking) != cudaSuccess) g_s2 = nullptr;
        if (cudaEventCreateWithFlags(&g_ev1, cudaEventDisableTiming) != cudaSuccess) g_ev1 = nullptr;
        if (cudaEventCreateWithFlags(&g_ev2, cudaEventDisableTiming) != cudaSuccess) g_ev2 = nullptr;
    }
};
StreamInit g_stream_init;
}

// ---------------- device helpers ----------------
__device__ __forceinline__ float fexp(float x) {
    x = fmaxf(x, -80.0f);
    float t = x * 1.4426950408889634f;
    float r = rintf(t);
    float f = t - r;
    float p = 1.3333558146e-3f;
    p = fmaf(p, f, 9.6181291076e-3f);
    p = fmaf(p, f, 5.5504108665e-2f);
    p = fmaf(p, f, 2.4022650696e-1f);
    p = fmaf(p, f, 6.9314718056e-1f);
    p = fmaf(p, f, 1.0f);
    int e = (int)r;
    return p * __int_as_float((e + 127) << 23);
}

__device__ __forceinline__ float gelu_f(float v) {
    return 0.5f * v * (1.0f + erff(v * 0.7071067811865476f));
}

__device__ __forceinline__ uint32_t f2tf(float x) {
    uint32_t r;
    asm("cvt.rna.tf32.f32 %0, %1;" : "=r"(r) : "f"(x));
    return r;
}

__device__ __forceinline__ uint32_t pkbf(float lo, float hi) {
    uint32_t r;
    asm("cvt.rn.bf16x2.f32 %0, %1, %2;" : "=r"(r) : "f"(hi), "f"(lo));
    return r;
}

__device__ __forceinline__ void mma_tf32(float c[4],
    uint32_t a0, uint32_t a1, uint32_t a2, uint32_t a3,
    uint32_t b0, uint32_t b1)
{
    asm volatile(
        "mma.sync.aligned.m16n8k8.row.col.f32.tf32.tf32.f32 "
        "{%0,%1,%2,%3}, {%4,%5,%6,%7}, {%8,%9}, {%0,%1,%2,%3};"
        : "+f"(c[0]), "+f"(c[1]), "+f"(c[2]), "+f"(c[3])
        : "r"(a0), "r"(a1), "r"(a2), "r"(a3), "r"(b0), "r"(b1));
}

__device__ __forceinline__ void mma_bf16(float c[4],
    uint32_t a0, uint32_t a1, uint32_t a2, uint32_t a3,
    uint32_t b0, uint32_t b1)
{
    asm volatile(
        "mma.sync.aligned.m16n8k16.row.col.f32.bf16.bf16.f32 "
        "{%0,%1,%2,%3}, {%4,%5,%6,%7}, {%8,%9}, {%0,%1,%2,%3};"
        : "+f"(c[0]), "+f"(c[1]), "+f"(c[2]), "+f"(c[3])
        : "r"(a0), "r"(a1), "r"(a2), "r"(a3), "r"(b0), "r"(b1));
}

__device__ __forceinline__ void cpa16(void* smem_dst, const void* gsrc) {
    uint32_t s = (uint32_t)__cvta_generic_to_shared(smem_dst);
    asm volatile("cp.async.cg.shared.global [%0], [%1], 16;" :: "r"(s), "l"(gsrc));
}

// ---------------- LayerNorm ----------------
__global__ void ln_kernel(const float* __restrict__ x, const float* __restrict__ gamma,
                          const float* __restrict__ beta, float* __restrict__ out) {
    int row = blockIdx.x;
    int t = threadIdx.x;
    float v = x[(size_t)row * DIM + t];
    float s = v, s2 = v * v;
    #pragma unroll
    for (int o = 16; o > 0; o >>= 1) {
        s  += __shfl_down_sync(0xffffffffu, s,  o);
        s2 += __shfl_down_sync(0xffffffffu, s2, o);
    }
    __shared__ float sh1[6], sh2[6];
    if ((t & 31) == 0) { sh1[t >> 5] = s; sh2[t >> 5] = s2; }
    __syncthreads();
    float ts = 0.f, ts2 = 0.f;
    #pragma unroll
    for (int i = 0; i < 6; i++) { ts += sh1[i]; ts2 += sh2[i]; }
    float mu  = ts * (1.0f / DIM);
    float var = ts2 * (1.0f / DIM) - mu * mu;
    float inv = rsqrtf(var + 1e-5f);
    out[(size_t)row * DIM + t] = (v - mu) * inv * gamma[t] + beta[t];
}

// ---------------- tensor-core GEMM: 128x64x16, 3-stage cp.async, tf32 (R12-proven) --
template <int EPI>
__global__ void __launch_bounds__(256) tgemm_k(
    const float* __restrict__ A, const float* __restrict__ B,
    const float* __restrict__ bias, const float* __restrict__ D,
    float* __restrict__ C, int M, int N, int K, int ldc, int ldd,
    size_t sA, size_t sB, size_t sD, size_t sC)
{
    __shared__ float As[3][128][20];
    __shared__ float Bs[3][16][72];
    int tid = threadIdx.x;
    int row0 = blockIdx.y * 128, col0 = blockIdx.x * 64;
    int z = blockIdx.z;
    int warp = tid >> 5, lane = tid & 31;
    int wm = (warp >> 1) * 32, wn = (warp & 1) * 32;
    int grp = lane >> 2, qid = lane & 3;

    int ar = tid >> 2, aseg = (tid & 3) << 2;
    int br = tid >> 4, bseg = (tid & 15) << 2;

    const float* Ap = A + (size_t)z * sA + (size_t)row0 * K;
    const float* Bp = B + (size_t)z * sB + col0;
    const float* Dp = D + (size_t)z * sD;
    float*       Cp = C + (size_t)z * sC;

    float acc[2][4][4];
    #pragma unroll
    for (int i = 0; i < 2; i++)
        #pragma unroll
        for (int j = 0; j < 4; j++)
            #pragma unroll
            for (int r = 0; r < 4; r++) acc[i][j][r] = 0.f;

    int T = K >> 4;

    #define PREFETCH(k0, bufi) do { \
        cpa16(&As[bufi][ar][aseg],      Ap + (size_t)ar * K + (k0) + aseg); \
        cpa16(&As[bufi][ar + 64][aseg], Ap + (size_t)(ar + 64) * K + (k0) + aseg); \
        cpa16(&Bs[bufi][br][bseg],      Bp + (size_t)((k0) + br) * N + bseg); \
        asm volatile("cp.async.commit_group;"); } while (0)

    PREFETCH(0, 0);
    PREFETCH(16, 1);
    for (int t = 0; t < T; t++) {
        if (t + 1 < T) asm volatile("cp.async.wait_group 1;");
        else           asm volatile("cp.async.wait_group 0;");
        __syncthreads();
        if (t + 2 < T) PREFETCH((t + 2) << 4, (t + 2) % 3);
        int buf = t % 3;
        #pragma unroll
        for (int ks = 0; ks < 2; ks++) {
            int kb = ks * 8;
            uint32_t af[2][4], bf[4][2];
            #pragma unroll
            for (int i = 0; i < 2; i++) {
                int m0 = wm + i * 16;
                af[i][0] = f2tf(As[buf][m0 + grp    ][kb + qid    ]);
                af[i][1] = f2tf(As[buf][m0 + grp + 8][kb + qid    ]);
                af[i][2] = f2tf(As[buf][m0 + grp    ][kb + qid + 4]);
                af[i][3] = f2tf(As[buf][m0 + grp + 8][kb + qid + 4]);
            }
            #pragma unroll
            for (int j = 0; j < 4; j++) {
                int n0 = wn + j * 8;
                bf[j][0] = f2tf(Bs[buf][kb + qid    ][n0 + grp]);
                bf[j][1] = f2tf(Bs[buf][kb + qid + 4][n0 + grp]);
            }
            #pragma unroll
            for (int i = 0; i < 2; i++)
                #pragma unroll
                for (int j = 0; j < 4; j++)
                    mma_tf32(acc[i][j], af[i][0], af[i][1], af[i][2], af[i][3],
                             bf[j][0], bf[j][1]);
        }
        __syncthreads();
    }
    #undef PREFETCH

    #pragma unroll
    for (int i = 0; i < 2; i++) {
        #pragma unroll
        for (int hh = 0; hh < 2; hh++) {
            int r = row0 + wm + i * 16 + grp + hh * 8;
            #pragma unroll
            for (int j = 0; j < 4; j++) {
                int cl = col0 + wn + j * 8 + qid * 2;
                float v0 = acc[i][j][hh * 2 + 0];
                float v1 = acc[i][j][hh * 2 + 1];
                if (bias) { float2 bb = *(const float2*)(bias + cl); v0 += bb.x; v1 += bb.y; }
                if (EPI == 1) { v0 = gelu_f(v0); v1 = gelu_f(v1); }
                if (EPI == 2) {
                    float2 dd = *(const float2*)(Dp + (size_t)r * ldd + cl);
                    v0 += dd.x; v1 += dd.y;
                }
                float2 ov; ov.x = v0; ov.y = v1;
                *(float2*)(Cp + (size_t)r * ldc + cl) = ov;
            }
        }
    }
}

// ---------------- q projection ----------------
__global__ void qproj_kernel(const float* __restrict__ xn, const float* __restrict__ wq,
                             const float* __restrict__ bq, float* __restrict__ q) {
    int idx = blockIdx.x * 256 + threadIdx.x;
    if (idx >= TOT * RD) return;
    int tok = idx / RD, j = idx % RD;
    const float* xr = xn + (size_t)tok * DIM;
    float s0 = 0.f, s1 = 0.f, s2 = 0.f, s3 = 0.f;
    #pragma unroll 4
    for (int k = 0; k < DIM; k += 4) {
        s0 = fmaf(xr[k + 0], wq[(k + 0) * RD + j], s0);
        s1 = fmaf(xr[k + 1], wq[(k + 1) * RD + j], s1);
        s2 = fmaf(xr[k + 2], wq[(k + 2) * RD + j], s2);
        s3 = fmaf(xr[k + 3], wq[(k + 3) * RD + j], s3);
    }
    q[idx] = bq[j] + (s0 + s1) + (s2 + s3);
}

// ---------------- dictionary prep ----------------
__global__ void tdprep_kernel(const float* __restrict__ td,
                              const float* __restrict__ wk, const float* __restrict__ bk,
                              const float* __restrict__ wv, const float* __restrict__ bv,
                              const float* __restrict__ wtd, const float* __restrict__ btd,
                              float* __restrict__ kn, float* __restrict__ vout,
                              float* __restrict__ tdf) {
    int bm = blockIdx.x;
    int t = threadIdx.x;
    __shared__ float tr[DIM];
    __shared__ float kr[RD];
    __shared__ float sinv;
    tr[t] = td[(size_t)bm * DIM + t];
    __syncthreads();
    if (t < RD) {
        float s0 = 0.f, s1 = 0.f, s2 = 0.f, s3 = 0.f;
        #pragma unroll 4
        for (int k = 0; k < DIM; k += 4) {
            s0 = fmaf(tr[k + 0], wk[(k + 0) * RD + t], s0);
            s1 = fmaf(tr[k + 1], wk[(k + 1) * RD + t], s1);
            s2 = fmaf(tr[k + 2], wk[(k + 2) * RD + t], s2);
            s3 = fmaf(tr[k + 3], wk[(k + 3) * RD + t], s3);
        }
        kr[t] = bk[t] + (s0 + s1) + (s2 + s3);
    }
    {
        float s0 = 0.f, s1 = 0.f, s2 = 0.f, s3 = 0.f;
        #pragma unroll 4
        for (int k = 0; k < DIM; k += 4) {
            s0 = fmaf(tr[k + 0], wv[(k + 0) * DIM + t], s0);
            s1 = fmaf(tr[k + 1], wv[(k + 1) * DIM + t], s1);
            s2 = fmaf(tr[k + 2], wv[(k + 2) * DIM + t], s2);
            s3 = fmaf(tr[k + 3], wv[(k + 3) * DIM + t], s3);
        }
        vout[(size_t)bm * DIM + t] = bv[t] + (s0 + s1) + (s2 + s3);
    }
    if (t < DTD) {
        float s0 = 0.f, s1 = 0.f, s2 = 0.f, s3 = 0.f;
        #pragma unroll 4
        for (int k = 0; k < DIM; k += 4) {
            s0 = fmaf(tr[k + 0], wtd[(k + 0) * DTD + t], s0);
            s1 = fmaf(tr[k + 1], wtd[(k + 1) * DTD + t], s1);
            s2 = fmaf(tr[k + 2], wtd[(k + 2) * DTD + t], s2);
            s3 = fmaf(tr[k + 3], wtd[(k + 3) * DTD + t], s3);
        }
        tdf[(size_t)bm * DTD + t] = btd[t] + (s0 + s1) + (s2 + s3);
    }
    __syncthreads();
    if (t == 0) {
        float n = 0.f;
        for (int i = 0; i < RD; i++) n += kr[i] * kr[i];
        sinv = 1.0f / fmaxf(sqrtf(n), 1e-12f);
    }
    __syncthreads();
    if (t < RD) kn[bm * RD + t] = kr[t] * sinv;
}

// ---------------- ATD cross-attn ----------------
__global__ void atd_kernel(const float* __restrict__ q, const float* __restrict__ kn,
                           const float* __restrict__ scale_p,
                           float* __restrict__ sim, int* __restrict__ tkid) {
    int tok = blockIdx.x;
    int b = tok >> 14;
    int t = threadIdx.x;
    int w = t >> 5, lane = t & 31;
    __shared__ float qn[RD];
    __shared__ float wmax[2]; __shared__ int widx[2];
    __shared__ float wsum[2];
    __shared__ float red0, red1;
    if (t == 0) {
        float qq[RD]; float n = 0.f;
        #pragma unroll
        for (int i = 0; i < RD; i++) { qq[i] = q[(size_t)tok * RD + i]; n += qq[i] * qq[i]; }
        float inv = 1.0f / fmaxf(sqrtf(n), 1e-12f);
        #pragma unroll
        for (int i = 0; i < RD; i++) qn[i] = qq[i] * inv;
    }
    __syncthreads();
    float sc = 1.0f + fminf(fmaxf(scale_p[0], 0.0f), 3.0f) * 4.1588830833596715f;
    const float* kr = kn + ((size_t)b * NDICT + t) * RD;
    float s = 0.f;
    #pragma unroll
    for (int i = 0; i < RD; i++) s = fmaf(qn[i], kr[i], s);
    float sv = s * sc;

    float mv = sv; int mi = t;
    #pragma unroll
    for (int o = 16; o > 0; o >>= 1) {
        float ov = __shfl_down_sync(0xffffffffu, mv, o);
        int   oi = __shfl_down_sync(0xffffffffu, mi, o);
        if (ov > mv || (ov == mv && oi < mi)) { mv = ov; mi = oi; }
    }
    if (lane == 0) { wmax[w] = mv; widx[w] = mi; }
    __syncthreads();
    if (t == 0) {
        float m0 = wmax[0], m1 = wmax[1];
        int am = (m1 > m0) ? widx[1] : widx[0];
        red0 = fmaxf(m0, m1);
        tkid[tok] = am;
    }
    __syncthreads();
    float e = fexp(sv - red0);
    float es = e;
    #pragma unroll
    for (int o = 16; o > 0; o >>= 1) es += __shfl_down_sync(0xffffffffu, es, o);
    if (lane == 0) wsum[w] = es;
    __syncthreads();
    if (t == 0) red1 = 1.0f / (wsum[0] + wsum[1]);
    __syncthreads();
    sim[(size_t)tok * NDICT + t] = e * red1;
}

// ---------------- stable counting sort ----------------
__global__ void hist_kernel(const int* __restrict__ tkid, int* __restrict__ off) {
    int b = blockIdx.x;
    __shared__ int h[NDICT];
    int t = threadIdx.x;
    if (t < NDICT) h[t] = 0;
    __syncthreads();
    for (int i = t; i < NTOKS; i += 256) atomicAdd(&h[tkid[b * NTOKS + i]], 1);
    __syncthreads();
    if (t == 0) {
        int acc = 0;
        for (int k = 0; k < NDICT; k++) { off[b * NDICT + k] = acc; acc += h[k]; }
    }
}

__global__ void scatter_kernel(const int* __restrict__ tkid, const int* __restrict__ off,
                               int* __restrict__ sidx) {
    int b = blockIdx.x >> 6, key = blockIdx.x & 63;
    const int* ids = tkid + b * NTOKS;
    int base = off[b * NDICT + key];
    int t = threadIdx.x, lane = t & 31, w = t >> 5;
    __shared__ int wc[8];
    for (int c = 0; c < NTOKS; c += 256) {
        int id = ids[c + t];
        bool f = (id == key);
        unsigned m = __ballot_sync(0xffffffffu, f);
        if (lane == 0) wc[w] = __popc(m);
        __syncthreads();
        int pre = 0, tot = 0;
        #pragma unroll
        for (int i = 0; i < 8; i++) { int cnt = wc[i]; tot += cnt; if (i < w) pre += cnt; }
        if (f) sidx[b * NTOKS + base + pre + __popc(m & ((1u << lane) - 1))] = c + t;
        base += tot;
        __syncthreads();
    }
}

// ---------------- AC_MSA via tensor-core MMA ----------------
__global__ void __launch_bounds__(256) acmsa_mma_kernel(
    const float* __restrict__ qkv, const int* __restrict__ sidx,
    float* __restrict__ ycat)
{
    __shared__ __align__(16) char smem_raw[27136];
    float* sQ = (float*)smem_raw;
    float* sK = (float*)smem_raw;
    __nv_bfloat16* sVT = (__nv_bfloat16*)(smem_raw + 18432);
    uint32_t* vtw = (uint32_t*)(smem_raw + 18432);

    int g = blockIdx.x, head = blockIdx.y, b = blockIdx.z;
    int tid = threadIdx.x;
    int warp = tid >> 5, lane = tid & 31;
    int grp = lane >> 2, qid = lane & 3;
    int q0 = warp * 16;
    const int* sp = sidx + b * NTOKS + g * GS;

    {
        int r = tid >> 1, off = (tid & 1) * 16;
        int tok = sp[r];
        const float4* src = (const float4*)(qkv + ((size_t)(b * NTOKS + tok)) * H3
                                            + head * HD + off);
        #pragma unroll
        for (int u = 0; u < 4; u++) {
            float4 v = src[u];
            float* d = sQ + r * 36 + off + u * 4;
            d[0] = v.x * 0.17677669529663687f;
            d[1] = v.y * 0.17677669529663687f;
            d[2] = v.z * 0.17677669529663687f;
            d[3] = v.w * 0.17677669529663687f;
        }
    }
    __syncthreads();

    uint32_t qa[4][4];
    #pragma unroll
    for (int ks = 0; ks < 4; ks++) {
        qa[ks][0] = f2tf(sQ[(q0 + grp    ) * 36 + ks * 8 + qid    ]);
        qa[ks][1] = f2tf(sQ[(q0 + grp + 8) * 36 + ks * 8 + qid    ]);
        qa[ks][2] = f2tf(sQ[(q0 + grp    ) * 36 + ks * 8 + qid + 4]);
        qa[ks][3] = f2tf(sQ[(q0 + grp + 8) * 36 + ks * 8 + qid + 4]);
    }
    int tok0 = sp[q0 + grp], tok1 = sp[q0 + grp + 8];

    float o[4][4];
    #pragma unroll
    for (int nt = 0; nt < 4; nt++)
        #pragma unroll
        for (int r = 0; r < 4; r++) o[nt][r] = 0.f;
    float m0v = -1e30f, m1v = -1e30f, l0 = 0.f, l1 = 0.f;
    __syncthreads();

    {
        int key = tid >> 1, part = tid & 1;
        int tok = sp[key];
        const float* basep = qkv + ((size_t)(b * NTOKS + tok)) * H3 + head * HD;
        const float4* ksrc = (const float4*)(basep + DIM + part * 16);
        float* kd = sK + key * 36 + part * 16;
        #pragma unroll
        for (int u = 0; u < 4; u++) {
            float4 kv = ksrc[u];
            kd[u * 4 + 0] = kv.x; kd[u * 4 + 1] = kv.y;
            kd[u * 4 + 2] = kv.z; kd[u * 4 + 3] = kv.w;
        }
        const float4* vsrc = (const float4*)(basep + 2 * DIM + part * 16);
        int d0 = part * 16;
        #pragma unroll
        for (int u = 0; u < 4; u++) {
            float4 vv = vsrc[u];
            sVT[(d0 + u * 4 + 0) * 136 + key] = __float2bfloat16(vv.x);
            sVT[(d0 + u * 4 + 1) * 136 + key] = __float2bfloat16(vv.y);
            sVT[(d0 + u * 4 + 2) * 136 + key] = __float2bfloat16(vv.z);
            sVT[(d0 + u * 4 + 3) * 136 + key] = __float2bfloat16(vv.w);
        }
    }
    __syncthreads();

    for (int kc = 0; kc < 4; kc++) {
        float s[4][4];
        #pragma unroll
        for (int nt = 0; nt < 4; nt++)
            #pragma unroll
            for (int r = 0; r < 4; r++) s[nt][r] = 0.f;
        #pragma unroll
        for (int nt = 0; nt < 4; nt++) {
            int krow = (kc * 32 + nt * 8 + grp) * 36;
            #pragma unroll
            for (int ks = 0; ks < 4; ks++) {
                uint32_t b0 = f2tf(sK[krow + ks * 8 + qid]);
                uint32_t b1 = f2tf(sK[krow + ks * 8 + qid + 4]);
                mma_tf32(s[nt], qa[ks][0], qa[ks][1], qa[ks][2], qa[ks][3], b0, b1);
            }
        }
        float mx0 = fmaxf(fmaxf(s[0][0], s[0][1]), fmaxf(s[1][0], s[1][1]));
        mx0 = fmaxf(mx0, fmaxf(fmaxf(s[2][0], s[2][1]), fmaxf(s[3][0], s[3][1])));
        float mx1 = fmaxf(fmaxf(s[0][2], s[0][3]), fmaxf(s[1][2], s[1][3]));
        mx1 = fmaxf(mx1, fmaxf(fmaxf(s[2][2], s[2][3]), fmaxf(s[3][2], s[3][3])));
        mx0 = fmaxf(mx0, __shfl_xor_sync(0xffffffffu, mx0, 1));
        mx0 = fmaxf(mx0, __shfl_xor_sync(0xffffffffu, mx0, 2));
        mx1 = fmaxf(mx1, __shfl_xor_sync(0xffffffffu, mx1, 1));
        mx1 = fmaxf(mx1, __shfl_xor_sync(0xffffffffu, mx1, 2));
        float mn0 = fmaxf(m0v, mx0), mn1 = fmaxf(m1v, mx1);
        float f0 = fexp(m0v - mn0), f1 = fexp(m1v - mn1);
        m0v = mn0; m1v = mn1;
        l0 *= f0; l1 *= f1;
        #pragma unroll
        for (int nt = 0; nt < 4; nt++) {
            o[nt][0] *= f0; o[nt][1] *= f0;
            o[nt][2] *= f1; o[nt][3] *= f1;
        }
        float ps0 = 0.f, ps1 = 0.f;
        #pragma unroll
        for (int nt = 0; nt < 4; nt++) {
            s[nt][0] = fexp(s[nt][0] - mn0); ps0 += s[nt][0];
            s[nt][1] = fexp(s[nt][1] - mn0); ps0 += s[nt][1];
            s[nt][2] = fexp(s[nt][2] - mn1); ps1 += s[nt][2];
            s[nt][3] = fexp(s[nt][3] - mn1); ps1 += s[nt][3];
        }
        l0 += ps0; l1 += ps1;
        #pragma unroll
        for (int ks = 0; ks < 2; ks++) {
            uint32_t a0 = pkbf(s[2 * ks][0],     s[2 * ks][1]);
            uint32_t a1 = pkbf(s[2 * ks][2],     s[2 * ks][3]);
            uint32_t a2 = pkbf(s[2 * ks + 1][0], s[2 * ks + 1][1]);
            uint32_t a3 = pkbf(s[2 * ks + 1][2], s[2 * ks + 1][3]);
            #pragma unroll
            for (int ntd = 0; ntd < 4; ntd++) {
                int base = (ntd * 8 + grp) * 68 + kc * 16 + ks * 8 + qid;
                mma_bf16(o[ntd], a0, a1, a2, a3, vtw[base], vtw[base + 4]);
            }
        }
    }
    l0 += __shfl_xor_sync(0xffffffffu, l0, 1);
    l0 += __shfl_xor_sync(0xffffffffu, l0, 2);
    l1 += __shfl_xor_sync(0xffffffffu, l1, 1);
    l1 += __shfl_xor_sync(0xffffffffu, l1, 2);
    float inv0 = 1.0f / l0, inv1 = 1.0f / l1;
    float* out0 = ycat + ((size_t)(b * NTOKS + tok0)) * YC + DIM + head * HD;
    float* out1 = ycat + ((size_t)(b * NTOKS + tok1)) * YC + DIM + head * HD;
    #pragma unroll
    for (int nt = 0; nt < 4; nt++) {
        float2 w0; w0.x = o[nt][0] * inv0; w0.y = o[nt][1] * inv0;
        float2 w1; w1.x = o[nt][2] * inv1; w1.y = o[nt][3] * inv1;
        *(float2*)(out0 + nt * 8 + 2 * qid) = w0;
        *(float2*)(out1 + nt * 8 + 2 * qid) = w1;
    }
}

// ---------------- transposed relative position bias ----------------
__global__ void rpbt_kernel(const int* __restrict__ rpi, const float* __restrict__ table,
                            float* __restrict__ rpbT) {
    int idx = blockIdx.x * 256 + threadIdx.x;
    if (idx >= NHEAD * WIN * WIN) return;
    int h = idx >> 16;
    int r = idx & 65535;
    int kj = r >> 8, qi = r & 255;
    rpbT[idx] = table[rpi[qi * WIN + kj] * NHEAD + h];
}

// ---------------- shifted-window attention via MMA ----------------
__global__ void __launch_bounds__(512) winattn_mma_kernel(
    const float* __restrict__ qkv, const float* __restrict__ mask,
    const float* __restrict__ rpbT, float* __restrict__ ycat)
{
    __shared__ __align__(16) char smem_raw[36864];
    float* sQ = (float*)smem_raw;
    float* sK = (float*)smem_raw;
    __nv_bfloat16* sVT = (__nv_bfloat16*)(smem_raw + 18432);
    uint32_t* vtw = (uint32_t*)(smem_raw + 18432);

    int wl = blockIdx.x, head = blockIdx.y, b = blockIdx.z;
    int wy = wl >> 3, wx = wl & 7;
    int tid = threadIdx.x;
    int warp = tid >> 5, lane = tid & 31;
    int grp = lane >> 2, qid = lane & 3;
    int q0 = warp * 16;

    {
        int r = tid >> 1, off = (tid & 1) * 16;
        int i = r >> 4, j = r & 15;
        int n = (((wy * WS + i + SS) & 127) << 7) | ((wx * WS + j + SS) & 127);
        const float4* src = (const float4*)(qkv + ((size_t)(b * NTOKS + n)) * H3
                                            + head * HD + off);
        #pragma unroll
        for (int u = 0; u < 4; u++) {
            float4 v = src[u];
            float* d = sQ + r * 36 + off + u * 4;
            d[0] = v.x * 0.17677669529663687f;
            d[1] = v.y * 0.17677669529663687f;
            d[2] = v.z * 0.17677669529663687f;
            d[3] = v.w * 0.17677669529663687f;
        }
    }
    __syncthreads();

    uint32_t qa[4][4];
    #pragma unroll
    for (int ks = 0; ks < 4; ks++) {
        qa[ks][0] = f2tf(sQ[(q0 + grp    ) * 36 + ks * 8 + qid    ]);
        qa[ks][1] = f2tf(sQ[(q0 + grp + 8) * 36 + ks * 8 + qid    ]);
        qa[ks][2] = f2tf(sQ[(q0 + grp    ) * 36 + ks * 8 + qid + 4]);
        qa[ks][3] = f2tf(sQ[(q0 + grp + 8) * 36 + ks * 8 + qid + 4]);
    }
    int r0 = q0 + grp, r1 = r0 + 8;
    int i0 = r0 >> 4, j0 = r0 & 15;
    int i1 = r1 >> 4, j1 = r1 & 15;
    int tok0 = (((wy * WS + i0 + SS) & 127) << 7) | ((wx * WS + j0 + SS) & 127);
    int tok1 = (((wy * WS + i1 + SS) & 127) << 7) | ((wx * WS + j1 + SS) & 127);
    const float* rpbh  = rpbT + (size_t)head * (WIN * WIN);
    const float* maskw = mask + (size_t)wl * (WIN * WIN);

    float o[4][4];
    #pragma unroll
    for (int nt = 0; nt < 4; nt++)
        #pragma unroll
        for (int r = 0; r < 4; r++) o[nt][r] = 0.f;
    float m0v = -1e30f, m1v = -1e30f, l0 = 0.f, l1 = 0.f;
    __syncthreads();

    for (int kt = 0; kt < 2; kt++) {
        {
            int key = tid >> 2, part = tid & 3;
            int p = kt * 128 + key;
            int pi = p >> 4, pj = p & 15;
            int np = (((wy * WS + pi + SS) & 127) << 7) | ((wx * WS + pj + SS) & 127);
            const float* basep = qkv + ((size_t)(b * NTOKS + np)) * H3 + head * HD;
            const float4* ksrc = (const float4*)(basep + DIM + part * 8);
            float4 k0 = ksrc[0], k1 = ksrc[1];
            float* kd = sK + key * 36 + part * 8;
            kd[0] = k0.x; kd[1] = k0.y; kd[2] = k0.z; kd[3] = k0.w;
            kd[4] = k1.x; kd[5] = k1.y; kd[6] = k1.z; kd[7] = k1.w;
            const float4* vsrc = (const float4*)(basep + 2 * DIM + part * 8);
            float4 v0 = vsrc[0], v1 = vsrc[1];
            int d0 = part * 8;
            sVT[(d0 + 0) * 136 + key] = __float2bfloat16(v0.x);
            sVT[(d0 + 1) * 136 + key] = __float2bfloat16(v0.y);
            sVT[(d0 + 2) * 136 + key] = __float2bfloat16(v0.z);
            sVT[(d0 + 3) * 136 + key] = __float2bfloat16(v0.w);
            sVT[(d0 + 4) * 136 + key] = __float2bfloat16(v1.x);
            sVT[(d0 + 5) * 136 + key] = __float2bfloat16(v1.y);
            sVT[(d0 + 6) * 136 + key] = __float2bfloat16(v1.z);
            sVT[(d0 + 7) * 136 + key] = __float2bfloat16(v1.w);
        }
        __syncthreads();

        for (int kc = 0; kc < 4; kc++) {
            int kbase = kt * 128 + kc * 32;
            float s[4][4];
            #pragma unroll
            for (int nt = 0; nt < 4; nt++)
                #pragma unroll
                for (int r = 0; r < 4; r++) s[nt][r] = 0.f;
            #pragma unroll
            for (int nt = 0; nt < 4; nt++) {
                int krow = (kc * 32 + nt * 8 + grp) * 36;
                #pragma unroll
                for (int ks = 0; ks < 4; ks++) {
                    uint32_t b0 = f2tf(sK[krow + ks * 8 + qid]);
                    uint32_t b1 = f2tf(sK[krow + ks * 8 + qid + 4]);
                    mma_tf32(s[nt], qa[ks][0], qa[ks][1], qa[ks][2], qa[ks][3], b0, b1);
                }
            }
            #pragma unroll
            for (int nt = 0; nt < 4; nt++) {
                int c0 = kbase + nt * 8 + 2 * qid;
                s[nt][0] += rpbh[c0 * WIN + r0] + maskw[c0 * WIN + r0];
                s[nt][1] += rpbh[(c0 + 1) * WIN + r0] + maskw[(c0 + 1) * WIN + r0];
                s[nt][2] += rpbh[c0 * WIN + r1] + maskw[c0 * WIN + r1];
                s[nt][3] += rpbh[(c0 + 1) * WIN + r1] + maskw[(c0 + 1) * WIN + r1];
            }
            float mx0 = fmaxf(fmaxf(s[0][0], s[0][1]), fmaxf(s[1][0], s[1][1]));
            mx0 = fmaxf(mx0, fmaxf(fmaxf(s[2][0], s[2][1]), fmaxf(s[3][0], s[3][1])));
            float mx1 = fmaxf(fmaxf(s[0][2], s[0][3]), fmaxf(s[1][2], s[1][3]));
            mx1 = fmaxf(mx1, fmaxf(fmaxf(s[2][2], s[2][3]), fmaxf(s[3][2], s[3][3])));
            mx0 = fmaxf(mx0, __shfl_xor_sync(0xffffffffu, mx0, 1));
            mx0 = fmaxf(mx0, __shfl_xor_sync(0xffffffffu, mx0, 2));
            mx1 = fmaxf(mx1, __shfl_xor_sync(0xffffffffu, mx1, 1));
            mx1 = fmaxf(mx1, __shfl_xor_sync(0xffffffffu, mx1, 2));
            float mn0 = fmaxf(m0v, mx0), mn1 = fmaxf(m1v, mx1);
            float f0 = fexp(m0v - mn0), f1 = fexp(m1v - mn1);
            m0v = mn0; m1v = mn1;
            l0 *= f0; l1 *= f1;
            #pragma unroll
            for (int nt = 0; nt < 4; nt++) {
                o[nt][0] *= f0; o[nt][1] *= f0;
                o[nt][2] *= f1; o[nt][3] *= f1;
            }
            float ps0 = 0.f, ps1 = 0.f;
            #pragma unroll
            for (int nt = 0; nt < 4; nt++) {
                s[nt][0] = fexp(s[nt][0] - mn0); ps0 += s[nt][0];
                s[nt][1] = fexp(s[nt][1] - mn0); ps0 += s[nt][1];
                s[nt][2] = fexp(s[nt][2] - mn1); ps1 += s[nt][2];
                s[nt][3] = fexp(s[nt][3] - mn1); ps1 += s[nt][3];
            }
            l0 += ps0; l1 += ps1;
            #pragma unroll
            for (int ks = 0; ks < 2; ks++) {
                uint32_t a0 = pkbf(s[2 * ks][0],     s[2 * ks][1]);
                uint32_t a1 = pkbf(s[2 * ks][2],     s[2 * ks][3]);
                uint32_t a2 = pkbf(s[2 * ks + 1][0], s[2 * ks + 1][1]);
                uint32_t a3 = pkbf(s[2 * ks + 1][2], s[2 * ks + 1][3]);
                #pragma unroll
                for (int ntd = 0; ntd < 4; ntd++) {
                    int base = (ntd * 8 + grp) * 68 + kc * 16 + ks * 8 + qid;
                    mma_bf16(o[ntd], a0, a1, a2, a3, vtw[base], vtw[base + 4]);
                }
            }
        }
        __syncthreads();
    }
    l0 += __shfl_xor_sync(0xffffffffu, l0, 1);
    l0 += __shfl_xor_sync(0xffffffffu, l0, 2);
    l1 += __shfl_xor_sync(0xffffffffu, l1, 1);
    l1 += __shfl_xor_sync(0xffffffffu, l1, 2);
    float inv0 = 1.0f / l0, inv1 = 1.0f / l1;
    float* out0 = ycat + ((size_t)(b * NTOKS + tok0)) * YC + head * HD;
    float* out1 = ycat + ((size_t)(b * NTOKS + tok1)) * YC + head * HD;
    #pragma unroll
    for (int nt = 0; nt < 4; nt++) {
        float2 w0; w0.x = o[nt][0] * inv0; w0.y = o[nt][1] * inv0;
        float2 w1; w1.x = o[nt][2] * inv1; w1.y = o[nt][3] * inv1;
        *(float2*)(out0 + nt * 8 + 2 * qid) = w0;
        *(float2*)(out1 + nt * 8 + 2 * qid) = w1;
    }
}

// ---------------- pack merged projection ----------------
__global__ void packproj_kernel(const float* __restrict__ ww, const float* __restrict__ wa,
                                const float* __restrict__ bw, const float* __restrict__ ba,
                                float* __restrict__ Bcat, float* __restrict__ bcat) {
    int idx = blockIdx.x * 256 + threadIdx.x;
    if (idx >= YC * DIM) return;
    int k = idx / DIM, n = idx % DIM;
    Bcat[idx] = (k < DIM) ? ww[k * DIM + n] : wa[(k - DIM) * DIM + n];
    if (idx < DIM) bcat[idx] = bw[idx] + ba[idx];
}

// ---------------- gather token-dict features ----------------
__global__ void gather_td_kernel(const float* __restrict__ tdf, const int* __restrict__ tkid,
                                 float* __restrict__ xc) {
    int idx = blockIdx.x * 256 + threadIdx.x;
    if (idx >= TOT * DTD) return;
    int tok = idx >> 6, j = idx & 63;
    int b = tok >> 14;
    xc[(size_t)tok * CH + MLPH + j] = tdf[((size_t)b * NDICT + tkid[tok]) * DTD + j];
}

// ---------------- depthwise 5x5 conv: 2 channels x 4 y-outputs per thread ----------
__global__ void dwconv_kernel(const float* __restrict__ xc, const float* __restrict__ w,
                              const float* __restrict__ bias, float* __restrict__ sout) {
    int u = blockIdx.x * 256 + threadIdx.x;
    if (u >= TOT * CH / 8) return;
    int cp = u % (CH / 2);
    int c = cp * 2;
    int p4 = u / (CH / 2);
    int x = p4 & 127, y4 = (p4 >> 7) & 31, b = p4 >> 12;
    int y0 = y4 << 2;
    float2 wr[25];
    #pragma unroll
    for (int i = 0; i < 25; i++) wr[i] = *(const float2*)(w + i * CH + c);
    float2 acc[4];
    #pragma unroll
    for (int r = 0; r < 4; r++) { acc[r].x = 0.f; acc[r].y = 0.f; }
    #pragma unroll
    for (int ry = 0; ry < 8; ry++) {
        int yy = y0 + ry - 2;
        if ((unsigned)yy >= 128u) continue;
        #pragma unroll
        for (int dx = 0; dx < 5; dx++) {
            int xx = x + dx - 2;
            if ((unsigned)xx >= 128u) continue;
            float2 v = *(const float2*)(xc + (size_t)((b << 14) | (yy << 7) | xx) * CH + c);
            #pragma unroll
            for (int r = 0; r < 4; r++) {
                int dy = ry - r;
                if (dy >= 0 && dy < 5) {
                    float2 ww2 = wr[dy * 5 + dx];
                    acc[r].x = fmaf(v.x, ww2.x, acc[r].x);
                    acc[r].y = fmaf(v.y, ww2.y, acc[r].y);
                }
            }
        }
    }
    float2 bc = *(const float2*)(bias + c);
    #pragma unroll
    for (int r = 0; r < 4; r++) {
        size_t idx = (size_t)((b << 14) | ((y0 + r) << 7) | x) * CH + c;
        float2 xv = *(const float2*)(xc + idx);
        float2 ov;
        ov.x = xv.x + gelu_f(acc[r].x + bc.x);
        ov.y = xv.y + gelu_f(acc[r].y + bc.y);
        *(float2*)(sout + idx) = ov;
    }
}

// ---------------- host side ----------------
static void sgemm(int epi, const float* A, const float* B, const float* bias, const float* D,
                  float* C, int M, int N, int K, int ldc, int ldd,
                  int nz = 1, size_t sA = 0, size_t sB = 0, size_t sD = 0, size_t sC = 0) {
    dim3 grid(N / 64, M / 128, nz), block(256);
    if (epi == 0)      tgemm_k<0><<<grid, block>>>(A, B, bias, D, C, M, N, K, ldc, ldd, sA, sB, sD, sC);
    else if (epi == 1) tgemm_k<1><<<grid, block>>>(A, B, bias, D, C, M, N, K, ldc, ldd, sA, sB, sD, sC);
    else               tgemm_k<2><<<grid, block>>>(A, B, bias, D, C, M, N, K, ldc, ldd, sA, sB, sD, sC);
}

extern "C" void kernel_launch(void* const* d_in, const int* in_sizes, int n_in,
                              void* d_out, int out_size) {
    (void)in_sizes; (void)out_size;
    const float* x         = (const float*)d_in[0];
    const float* td        = (const float*)d_in[1];
    const float* attn_mask = (const float*)d_in[2];
    const int*   rpi       = (const int*)  d_in[3];
    int base = (n_in >= 32) ? 6 : 4;
    const float* norm1_g    = (const float*)d_in[base + 0];
    const float* norm1_b    = (const float*)d_in[base + 1];
    const float* norm2_g    = (const float*)d_in[base + 2];
    const float* norm2_b    = (const float*)d_in[base + 3];
    const float* wqkv_w     = (const float*)d_in[base + 4];
    const float* wqkv_b     = (const float*)d_in[base + 5];
    const float* wq_w       = (const float*)d_in[base + 6];
    const float* wq_b       = (const float*)d_in[base + 7];
    const float* wk_w       = (const float*)d_in[base + 8];
    const float* wk_b       = (const float*)d_in[base + 9];
    const float* wv_w       = (const float*)d_in[base + 10];
    const float* wv_b       = (const float*)d_in[base + 11];
    const float* atd_scale  = (const float*)d_in[base + 12];
    const float* aca_proj_w = (const float*)d_in[base + 13];
    const float* aca_proj_b = (const float*)d_in[base + 14];
    const float* rpb_table  = (const float*)d_in[base + 15];
    const float* win_proj_w = (const float*)d_in[base + 16];
    const float* win_proj_b = (const float*)d_in[base + 17];
    const float* fc_td_w    = (const float*)d_in[base + 18];
    const float* fc_td_b    = (const float*)d_in[base + 19];
    const float* fc1_w      = (const float*)d_in[base + 20];
    const float* fc1_b      = (const float*)d_in[base + 21];
    const float* dw_w       = (const float*)d_in[base + 22];
    const float* dw_b       = (const float*)d_in[base + 23];
    const float* fc2_w      = (const float*)d_in[base + 24];
    const float* fc2_b      = (const float*)d_in[base + 25];

    float *xn, *qkv, *qb, *kn, *vb, *tdf, *sim, *ycat, *xs, *rpbT, *xc, *sb, *bcat, *bcatb;
    int *tkid, *sidx, *off;
    cudaGetSymbolAddress((void**)&xn,    g_xn);
    cudaGetSymbolAddress((void**)&qkv,   g_qkv);
    cudaGetSymbolAddress((void**)&qb,    g_q);
    cudaGetSymbolAddress((void**)&kn,    g_kn);
    cudaGetSymbolAddress((void**)&vb,    g_v);
    cudaGetSymbolAddress((void**)&tdf,   g_tdf);
    cudaGetSymbolAddress((void**)&sim,   g_sim);
    cudaGetSymbolAddress((void**)&tkid,  g_tkid);
    cudaGetSymbolAddress((void**)&sidx,  g_sidx);
    cudaGetSymbolAddress((void**)&off,   g_off);
    cudaGetSymbolAddress((void**)&ycat,  g_ycat);
    cudaGetSymbolAddress((void**)&xs,    g_xs);
    cudaGetSymbolAddress((void**)&rpbT,  g_rpbT);
    cudaGetSymbolAddress((void**)&xc,    g_xc);
    cudaGetSymbolAddress((void**)&sb,    g_s);
    cudaGetSymbolAddress((void**)&bcat,  g_bcat);
    cudaGetSymbolAddress((void**)&bcatb, g_bcatb);

    bool fork = (g_s2 != nullptr && g_ev1 != nullptr && g_ev2 != nullptr);

    // 1) LN1 + qkv GEMM on main stream
    ln_kernel<<<TOT, DIM>>>(x, norm1_g, norm1_b, xn);
    sgemm(0, xn, wqkv_w, wqkv_b, nullptr, qkv, TOT, H3, DIM, H3, 0);

    if (fork) {
        cudaEventRecord(g_ev1, 0);
        cudaStreamWaitEvent(g_s2, g_ev1, 0);
        packproj_kernel<<<(YC * DIM + 255) / 256, 256, 0, g_s2>>>(
            win_proj_w, aca_proj_w, win_proj_b, aca_proj_b, bcat, bcatb);
        rpbt_kernel<<<(NHEAD * WIN * WIN + 255) / 256, 256, 0, g_s2>>>(rpi, rpb_table, rpbT);
        winattn_mma_kernel<<<dim3(NWIN, NHEAD, BATCH), 512, 0, g_s2>>>(
            qkv, attn_mask, rpbT, ycat);
        cudaEventRecord(g_ev2, g_s2);
    }

    // main stream: ATD chain
    qproj_kernel<<<(TOT * RD + 255) / 256, 256>>>(xn, wq_w, wq_b, qb);
    tdprep_kernel<<<BATCH * NDICT, DIM>>>(td, wk_w, wk_b, wv_w, wv_b, fc_td_w, fc_td_b,
                                          kn, vb, tdf);
    atd_kernel<<<TOT, NDICT>>>(qb, kn, atd_scale, sim, tkid);
    sgemm(2, sim, vb, nullptr, x, xs, NTOKS, DIM, NDICT, DIM, DIM,
          BATCH, (size_t)NTOKS * NDICT, (size_t)NDICT * DIM,
          (size_t)NTOKS * DIM, (size_t)NTOKS * DIM);
    hist_kernel<<<BATCH, 256>>>(tkid, off);
    scatter_kernel<<<BATCH * NDICT, 256>>>(tkid, off, sidx);
    acmsa_mma_kernel<<<dim3(NG, NHEAD, BATCH), 256>>>(qkv, sidx, ycat);

    if (fork) {
        cudaStreamWaitEvent(0, g_ev2, 0);   // join
    } else {
        packproj_kernel<<<(YC * DIM + 255) / 256, 256>>>(win_proj_w, aca_proj_w,
                                                         win_proj_b, aca_proj_b, bcat, bcatb);
        rpbt_kernel<<<(NHEAD * WIN * WIN + 255) / 256, 256>>>(rpi, rpb_table, rpbT);
        winattn_mma_kernel<<<dim3(NWIN, NHEAD, BATCH), 512>>>(qkv, attn_mask, rpbT, ycat);
    }

    // merged projection + FFN tail
    sgemm(2, ycat, bcat, bcatb, xs, xs, TOT, DIM, YC, DIM, DIM);
    ln_kernel<<<TOT, DIM>>>(xs, norm2_g, norm2_b, xn);
    sgemm(1, xn, fc1_w, fc1_b, nullptr, xc, TOT, MLPH, DIM, CH, 0);
    gather_td_kernel<<<(TOT * DTD + 255) / 256, 256>>>(tdf, tkid, xc);
    dwconv_kernel<<<(TOT * CH / 8 + 255) / 256, 256>>>(xc, dw_w, dw_b, sb);
    sgemm(2, sb, fc2_w, fc2_b, xs, (float*)d_out, TOT, DIM, CH, DIM, DIM);
}

// round 15
// speedup vs baseline: 1.2059x; 1.0909x over previous
#include <cuda_runtime.h>
#include <cuda_bf16.h>
#include <cstdint>
#include <math.h>

// ---------------- problem constants ----------------
#define BATCH 4
#define IMGH 128
#define IMGW 128
#define NTOKS (IMGH*IMGW)
#define TOT (BATCH*NTOKS)
#define DIM 192
#define H3 576
#define NHEAD 6
#define HD 32
#define WS 16
#define SS 8
#define NWIN 64
#define WIN 256
#define NDICT 64
#define RD 10
#define DTD 64
#define MLPH 384
#define CH 448
#define GS 128
#define NG 128
#define YC 384

// ---------------- scratch ----------------
__device__ __align__(16) float g_xn  [TOT*DIM];
__device__ __align__(16) float g_qkv [TOT*H3];
__device__ __align__(16) float g_q   [TOT*RD];
__device__ __align__(16) float g_kn  [BATCH*NDICT*RD];
__device__ __align__(16) float g_v   [BATCH*NDICT*DIM];
__device__ __align__(16) float g_tdf [BATCH*NDICT*DTD];
__device__ __align__(16) float g_sim [TOT*NDICT];
__device__           int   g_tkid[TOT];
__device__           int   g_sidx[TOT];
__device__           int   g_off [BATCH*NDICT];
__device__ __align__(16) float g_ycat[TOT*YC];
__device__ __align__(16) float g_xs  [TOT*DIM];
__device__ __align__(16) float g_rpbT[NHEAD*WIN*WIN];
__device__ __align__(16) float g_xc  [TOT*CH];
__device__ __align__(16) float g_s   [TOT*CH];
__device__ __align__(16) float g_bcat[YC*DIM];
__device__ __align__(16) float g_bcatb[DIM];

// ---------------- side stream for fork/join (created at static init) ----------------
static cudaStream_t g_s2 = nullptr;
static cudaEvent_t g_ev1 = nullptr, g_ev2 = nullptr;
namespace {
struct StreamInit {
    StreamInit() {
        if (cudaStreamCreateWithFlags(&g_s2, cudaStreamNonBlocking) != cudaSuccess) g_s2 = nullptr;
        if (cudaEventCreateWithFlags(&g_ev1, cudaEventDisableTiming) != cudaSuccess) g_ev1 = nullptr;
        if (cudaEventCreateWithFlags(&g_ev2, cudaEventDisableTiming) != cudaSuccess) g_ev2 = nullptr;
    }
};
StreamInit g_stream_init;
}

// ---------------- device helpers ----------------
__device__ __forceinline__ float fexp(float x) {
    x = fmaxf(x, -80.0f);
    float t = x * 1.4426950408889634f;
    float r = rintf(t);
    float f = t - r;
    float p = 1.3333558146e-3f;
    p = fmaf(p, f, 9.6181291076e-3f);
    p = fmaf(p, f, 5.5504108665e-2f);
    p = fmaf(p, f, 2.4022650696e-1f);
    p = fmaf(p, f, 6.9314718056e-1f);
    p = fmaf(p, f, 1.0f);
    int e = (int)r;
    return p * __int_as_float((e + 127) << 23);
}

__device__ __forceinline__ float gelu_f(float v) {
    return 0.5f * v * (1.0f + erff(v * 0.7071067811865476f));
}

__device__ __forceinline__ uint32_t f2tf(float x) {
    uint32_t r;
    asm("cvt.rna.tf32.f32 %0, %1;" : "=r"(r) : "f"(x));
    return r;
}

__device__ __forceinline__ uint32_t pkbf(float lo, float hi) {
    uint32_t r;
    asm("cvt.rn.bf16x2.f32 %0, %1, %2;" : "=r"(r) : "f"(hi), "f"(lo));
    return r;
}

__device__ __forceinline__ void mma_tf32(float c[4],
    uint32_t a0, uint32_t a1, uint32_t a2, uint32_t a3,
    uint32_t b0, uint32_t b1)
{
    asm volatile(
        "mma.sync.aligned.m16n8k8.row.col.f32.tf32.tf32.f32 "
        "{%0,%1,%2,%3}, {%4,%5,%6,%7}, {%8,%9}, {%0,%1,%2,%3};"
        : "+f"(c[0]), "+f"(c[1]), "+f"(c[2]), "+f"(c[3])
        : "r"(a0), "r"(a1), "r"(a2), "r"(a3), "r"(b0), "r"(b1));
}

__device__ __forceinline__ void mma_bf16(float c[4],
    uint32_t a0, uint32_t a1, uint32_t a2, uint32_t a3,
    uint32_t b0, uint32_t b1)
{
    asm volatile(
        "mma.sync.aligned.m16n8k16.row.col.f32.bf16.bf16.f32 "
        "{%0,%1,%2,%3}, {%4,%5,%6,%7}, {%8,%9}, {%0,%1,%2,%3};"
        : "+f"(c[0]), "+f"(c[1]), "+f"(c[2]), "+f"(c[3])
        : "r"(a0), "r"(a1), "r"(a2), "r"(a3), "r"(b0), "r"(b1));
}

__device__ __forceinline__ void cpa16(void* smem_dst, const void* gsrc) {
    uint32_t s = (uint32_t)__cvta_generic_to_shared(smem_dst);
    asm volatile("cp.async.cg.shared.global [%0], [%1], 16;" :: "r"(s), "l"(gsrc));
}

// ---------------- LayerNorm: warp per token, float4, shuffle-only reduce ----------
__global__ void ln_kernel(const float* __restrict__ x, const float* __restrict__ gamma,
                          const float* __restrict__ beta, float* __restrict__ out) {
    int token = blockIdx.x * 8 + (threadIdx.x >> 5);
    int lane = threadIdx.x & 31;
    const float4* xr = (const float4*)(x + (size_t)token * DIM);   // 48 float4
    float4 v1 = xr[lane];
    float4 v2 = make_float4(0.f, 0.f, 0.f, 0.f);
    bool has2 = lane < 16;
    if (has2) v2 = xr[32 + lane];
    float s  = (v1.x + v1.y) + (v1.z + v1.w) + (v2.x + v2.y) + (v2.z + v2.w);
    float s2 = v1.x * v1.x + v1.y * v1.y + v1.z * v1.z + v1.w * v1.w
             + v2.x * v2.x + v2.y * v2.y + v2.z * v2.z + v2.w * v2.w;
    #pragma unroll
    for (int o = 16; o > 0; o >>= 1) {
        s  += __shfl_xor_sync(0xffffffffu, s,  o);
        s2 += __shfl_xor_sync(0xffffffffu, s2, o);
    }
    float mu  = s * (1.0f / DIM);
    float var = s2 * (1.0f / DIM) - mu * mu;
    float inv = rsqrtf(var + 1e-5f);
    const float4* g4 = (const float4*)gamma;
    const float4* b4 = (const float4*)beta;
    float4* o4 = (float4*)(out + (size_t)token * DIM);
    {
        float4 gg = g4[lane], bb = b4[lane], ov;
        ov.x = (v1.x - mu) * inv * gg.x + bb.x;
        ov.y = (v1.y - mu) * inv * gg.y + bb.y;
        ov.z = (v1.z - mu) * inv * gg.z + bb.z;
        ov.w = (v1.w - mu) * inv * gg.w + bb.w;
        o4[lane] = ov;
    }
    if (has2) {
        float4 gg = g4[32 + lane], bb = b4[32 + lane], ov;
        ov.x = (v2.x - mu) * inv * gg.x + bb.x;
        ov.y = (v2.y - mu) * inv * gg.y + bb.y;
        ov.z = (v2.z - mu) * inv * gg.z + bb.z;
        ov.w = (v2.w - mu) * inv * gg.w + bb.w;
        o4[32 + lane] = ov;
    }
}

// ---------------- tensor-core GEMM: 128x64x16, 3-stage cp.async, tf32 (proven) -----
template <int EPI>
__global__ void __launch_bounds__(256) tgemm_k(
    const float* __restrict__ A, const float* __restrict__ B,
    const float* __restrict__ bias, const float* __restrict__ D,
    float* __restrict__ C, int M, int N, int K, int ldc, int ldd,
    size_t sA, size_t sB, size_t sD, size_t sC)
{
    __shared__ float As[3][128][20];
    __shared__ float Bs[3][16][72];
    int tid = threadIdx.x;
    int row0 = blockIdx.y * 128, col0 = blockIdx.x * 64;
    int z = blockIdx.z;
    int warp = tid >> 5, lane = tid & 31;
    int wm = (warp >> 1) * 32, wn = (warp & 1) * 32;
    int grp = lane >> 2, qid = lane & 3;

    int ar = tid >> 2, aseg = (tid & 3) << 2;
    int br = tid >> 4, bseg = (tid & 15) << 2;

    const float* Ap = A + (size_t)z * sA + (size_t)row0 * K;
    const float* Bp = B + (size_t)z * sB + col0;
    const float* Dp = D + (size_t)z * sD;
    float*       Cp = C + (size_t)z * sC;

    float acc[2][4][4];
    #pragma unroll
    for (int i = 0; i < 2; i++)
        #pragma unroll
        for (int j = 0; j < 4; j++)
            #pragma unroll
            for (int r = 0; r < 4; r++) acc[i][j][r] = 0.f;

    int T = K >> 4;

    #define PREFETCH(k0, bufi) do { \
        cpa16(&As[bufi][ar][aseg],      Ap + (size_t)ar * K + (k0) + aseg); \
        cpa16(&As[bufi][ar + 64][aseg], Ap + (size_t)(ar + 64) * K + (k0) + aseg); \
        cpa16(&Bs[bufi][br][bseg],      Bp + (size_t)((k0) + br) * N + bseg); \
        asm volatile("cp.async.commit_group;"); } while (0)

    PREFETCH(0, 0);
    PREFETCH(16, 1);
    for (int t = 0; t < T; t++) {
        if (t + 1 < T) asm volatile("cp.async.wait_group 1;");
        else           asm volatile("cp.async.wait_group 0;");
        __syncthreads();
        if (t + 2 < T) PREFETCH((t + 2) << 4, (t + 2) % 3);
        int buf = t % 3;
        #pragma unroll
        for (int ks = 0; ks < 2; ks++) {
            int kb = ks * 8;
            uint32_t af[2][4], bf[4][2];
            #pragma unroll
            for (int i = 0; i < 2; i++) {
                int m0 = wm + i * 16;
                af[i][0] = f2tf(As[buf][m0 + grp    ][kb + qid    ]);
                af[i][1] = f2tf(As[buf][m0 + grp + 8][kb + qid    ]);
                af[i][2] = f2tf(As[buf][m0 + grp    ][kb + qid + 4]);
                af[i][3] = f2tf(As[buf][m0 + grp + 8][kb + qid + 4]);
            }
            #pragma unroll
            for (int j = 0; j < 4; j++) {
                int n0 = wn + j * 8;
                bf[j][0] = f2tf(Bs[buf][kb + qid    ][n0 + grp]);
                bf[j][1] = f2tf(Bs[buf][kb + qid + 4][n0 + grp]);
            }
            #pragma unroll
            for (int i = 0; i < 2; i++)
                #pragma unroll
                for (int j = 0; j < 4; j++)
                    mma_tf32(acc[i][j], af[i][0], af[i][1], af[i][2], af[i][3],
                             bf[j][0], bf[j][1]);
        }
        __syncthreads();
    }
    #undef PREFETCH

    #pragma unroll
    for (int i = 0; i < 2; i++) {
        #pragma unroll
        for (int hh = 0; hh < 2; hh++) {
            int r = row0 + wm + i * 16 + grp + hh * 8;
            #pragma unroll
            for (int j = 0; j < 4; j++) {
                int cl = col0 + wn + j * 8 + qid * 2;
                float v0 = acc[i][j][hh * 2 + 0];
                float v1 = acc[i][j][hh * 2 + 1];
                if (bias) { float2 bb = *(const float2*)(bias + cl); v0 += bb.x; v1 += bb.y; }
                if (EPI == 1) { v0 = gelu_f(v0); v1 = gelu_f(v1); }
                if (EPI == 2) {
                    float2 dd = *(const float2*)(Dp + (size_t)r * ldd + cl);
                    v0 += dd.x; v1 += dd.y;
                }
                float2 ov; ov.x = v0; ov.y = v1;
                *(float2*)(Cp + (size_t)r * ldc + cl) = ov;
            }
        }
    }
}

// ---------------- q projection (float4 xn loads) ----------------
__global__ void qproj_kernel(const float* __restrict__ xn, const float* __restrict__ wq,
                             const float* __restrict__ bq, float* __restrict__ q) {
    int idx = blockIdx.x * 256 + threadIdx.x;
    if (idx >= TOT * RD) return;
    int tok = idx / RD, j = idx % RD;
    const float4* x4 = (const float4*)(xn + (size_t)tok * DIM);
    float s0 = 0.f, s1 = 0.f, s2 = 0.f, s3 = 0.f;
    #pragma unroll 8
    for (int k4 = 0; k4 < DIM / 4; k4++) {
        float4 v = x4[k4];
        int k = k4 * 4;
        s0 = fmaf(v.x, wq[(k + 0) * RD + j], s0);
        s1 = fmaf(v.y, wq[(k + 1) * RD + j], s1);
        s2 = fmaf(v.z, wq[(k + 2) * RD + j], s2);
        s3 = fmaf(v.w, wq[(k + 3) * RD + j], s3);
    }
    q[idx] = bq[j] + (s0 + s1) + (s2 + s3);
}

// ---------------- dictionary prep ----------------
__global__ void tdprep_kernel(const float* __restrict__ td,
                              const float* __restrict__ wk, const float* __restrict__ bk,
                              const float* __restrict__ wv, const float* __restrict__ bv,
                              const float* __restrict__ wtd, const float* __restrict__ btd,
                              float* __restrict__ kn, float* __restrict__ vout,
                              float* __restrict__ tdf) {
    int bm = blockIdx.x;
    int t = threadIdx.x;
    __shared__ float tr[DIM];
    __shared__ float kr[RD];
    __shared__ float sinv;
    tr[t] = td[(size_t)bm * DIM + t];
    __syncthreads();
    if (t < RD) {
        float s0 = 0.f, s1 = 0.f, s2 = 0.f, s3 = 0.f;
        #pragma unroll 4
        for (int k = 0; k < DIM; k += 4) {
            s0 = fmaf(tr[k + 0], wk[(k + 0) * RD + t], s0);
            s1 = fmaf(tr[k + 1], wk[(k + 1) * RD + t], s1);
            s2 = fmaf(tr[k + 2], wk[(k + 2) * RD + t], s2);
            s3 = fmaf(tr[k + 3], wk[(k + 3) * RD + t], s3);
        }
        kr[t] = bk[t] + (s0 + s1) + (s2 + s3);
    }
    {
        float s0 = 0.f, s1 = 0.f, s2 = 0.f, s3 = 0.f;
        #pragma unroll 4
        for (int k = 0; k < DIM; k += 4) {
            s0 = fmaf(tr[k + 0], wv[(k + 0) * DIM + t], s0);
            s1 = fmaf(tr[k + 1], wv[(k + 1) * DIM + t], s1);
            s2 = fmaf(tr[k + 2], wv[(k + 2) * DIM + t], s2);
            s3 = fmaf(tr[k + 3], wv[(k + 3) * DIM + t], s3);
        }
        vout[(size_t)bm * DIM + t] = bv[t] + (s0 + s1) + (s2 + s3);
    }
    if (t < DTD) {
        float s0 = 0.f, s1 = 0.f, s2 = 0.f, s3 = 0.f;
        #pragma unroll 4
        for (int k = 0; k < DIM; k += 4) {
            s0 = fmaf(tr[k + 0], wtd[(k + 0) * DTD + t], s0);
            s1 = fmaf(tr[k + 1], wtd[(k + 1) * DTD + t], s1);
            s2 = fmaf(tr[k + 2], wtd[(k + 2) * DTD + t], s2);
            s3 = fmaf(tr[k + 3], wtd[(k + 3) * DTD + t], s3);
        }
        tdf[(size_t)bm * DTD + t] = btd[t] + (s0 + s1) + (s2 + s3);
    }
    __syncthreads();
    if (t == 0) {
        float n = 0.f;
        for (int i = 0; i < RD; i++) n += kr[i] * kr[i];
        sinv = 1.0f / fmaxf(sqrtf(n), 1e-12f);
    }
    __syncthreads();
    if (t < RD) kn[bm * RD + t] = kr[t] * sinv;
}

// ---------------- ATD cross-attn ----------------
__global__ void atd_kernel(const float* __restrict__ q, const float* __restrict__ kn,
                           const float* __restrict__ scale_p,
                           float* __restrict__ sim, int* __restrict__ tkid) {
    int tok = blockIdx.x;
    int b = tok >> 14;
    int t = threadIdx.x;
    int w = t >> 5, lane = t & 31;
    __shared__ float qn[RD];
    __shared__ float wmax[2]; __shared__ int widx[2];
    __shared__ float wsum[2];
    __shared__ float red0, red1;
    if (t == 0) {
        float qq[RD]; float n = 0.f;
        #pragma unroll
        for (int i = 0; i < RD; i++) { qq[i] = q[(size_t)tok * RD + i]; n += qq[i] * qq[i]; }
        float inv = 1.0f / fmaxf(sqrtf(n), 1e-12f);
        #pragma unroll
        for (int i = 0; i < RD; i++) qn[i] = qq[i] * inv;
    }
    __syncthreads();
    float sc = 1.0f + fminf(fmaxf(scale_p[0], 0.0f), 3.0f) * 4.1588830833596715f;
    const float* kr = kn + ((size_t)b * NDICT + t) * RD;
    float s = 0.f;
    #pragma unroll
    for (int i = 0; i < RD; i++) s = fmaf(qn[i], kr[i], s);
    float sv = s * sc;

    float mv = sv; int mi = t;
    #pragma unroll
    for (int o = 16; o > 0; o >>= 1) {
        float ov = __shfl_down_sync(0xffffffffu, mv, o);
        int   oi = __shfl_down_sync(0xffffffffu, mi, o);
        if (ov > mv || (ov == mv && oi < mi)) { mv = ov; mi = oi; }
    }
    if (lane == 0) { wmax[w] = mv; widx[w] = mi; }
    __syncthreads();
    if (t == 0) {
        float m0 = wmax[0], m1 = wmax[1];
        int am = (m1 > m0) ? widx[1] : widx[0];
        red0 = fmaxf(m0, m1);
        tkid[tok] = am;
    }
    __syncthreads();
    float e = fexp(sv - red0);
    float es = e;
    #pragma unroll
    for (int o = 16; o > 0; o >>= 1) es += __shfl_down_sync(0xffffffffu, es, o);
    if (lane == 0) wsum[w] = es;
    __syncthreads();
    if (t == 0) red1 = 1.0f / (wsum[0] + wsum[1]);
    __syncthreads();
    sim[(size_t)tok * NDICT + t] = e * red1;
}

// ---------------- stable counting sort ----------------
__global__ void hist_kernel(const int* __restrict__ tkid, int* __restrict__ off) {
    int b = blockIdx.x;
    __shared__ int h[NDICT];
    int t = threadIdx.x;
    if (t < NDICT) h[t] = 0;
    __syncthreads();
    for (int i = t; i < NTOKS; i += 256) atomicAdd(&h[tkid[b * NTOKS + i]], 1);
    __syncthreads();
    if (t == 0) {
        int acc = 0;
        for (int k = 0; k < NDICT; k++) { off[b * NDICT + k] = acc; acc += h[k]; }
    }
}

__global__ void scatter_kernel(const int* __restrict__ tkid, const int* __restrict__ off,
                               int* __restrict__ sidx) {
    int b = blockIdx.x >> 6, key = blockIdx.x & 63;
    const int* ids = tkid + b * NTOKS;
    int base = off[b * NDICT + key];
    int t = threadIdx.x, lane = t & 31, w = t >> 5;
    __shared__ int wc[8];
    for (int c = 0; c < NTOKS; c += 256) {
        int id = ids[c + t];
        bool f = (id == key);
        unsigned m = __ballot_sync(0xffffffffu, f);
        if (lane == 0) wc[w] = __popc(m);
        __syncthreads();
        int pre = 0, tot = 0;
        #pragma unroll
        for (int i = 0; i < 8; i++) { int cnt = wc[i]; tot += cnt; if (i < w) pre += cnt; }
        if (f) sidx[b * NTOKS + base + pre + __popc(m & ((1u << lane) - 1))] = c + t;
        base += tot;
        __syncthreads();
    }
}

// ---------------- AC_MSA via tensor-core MMA ----------------
__global__ void __launch_bounds__(256) acmsa_mma_kernel(
    const float* __restrict__ qkv, const int* __restrict__ sidx,
    float* __restrict__ ycat)
{
    __shared__ __align__(16) char smem_raw[27136];
    float* sQ = (float*)smem_raw;
    float* sK = (float*)smem_raw;
    __nv_bfloat16* sVT = (__nv_bfloat16*)(smem_raw + 18432);
    uint32_t* vtw = (uint32_t*)(smem_raw + 18432);

    int g = blockIdx.x, head = blockIdx.y, b = blockIdx.z;
    int tid = threadIdx.x;
    int warp = tid >> 5, lane = tid & 31;
    int grp = lane >> 2, qid = lane & 3;
    int q0 = warp * 16;
    const int* sp = sidx + b * NTOKS + g * GS;

    {
        int r = tid >> 1, off = (tid & 1) * 16;
        int tok = sp[r];
        const float4* src = (const float4*)(qkv + ((size_t)(b * NTOKS + tok)) * H3
                                            + head * HD + off);
        #pragma unroll
        for (int u = 0; u < 4; u++) {
            float4 v = src[u];
            float* d = sQ + r * 36 + off + u * 4;
            d[0] = v.x * 0.17677669529663687f;
            d[1] = v.y * 0.17677669529663687f;
            d[2] = v.z * 0.17677669529663687f;
            d[3] = v.w * 0.17677669529663687f;
        }
    }
    __syncthreads();

    uint32_t qa[4][4];
    #pragma unroll
    for (int ks = 0; ks < 4; ks++) {
        qa[ks][0] = f2tf(sQ[(q0 + grp    ) * 36 + ks * 8 + qid    ]);
        qa[ks][1] = f2tf(sQ[(q0 + grp + 8) * 36 + ks * 8 + qid    ]);
        qa[ks][2] = f2tf(sQ[(q0 + grp    ) * 36 + ks * 8 + qid + 4]);
        qa[ks][3] = f2tf(sQ[(q0 + grp + 8) * 36 + ks * 8 + qid + 4]);
    }
    int tok0 = sp[q0 + grp], tok1 = sp[q0 + grp + 8];

    float o[4][4];
    #pragma unroll
    for (int nt = 0; nt < 4; nt++)
        #pragma unroll
        for (int r = 0; r < 4; r++) o[nt][r] = 0.f;
    float m0v = -1e30f, m1v = -1e30f, l0 = 0.f, l1 = 0.f;
    __syncthreads();

    {
        int key = tid >> 1, part = tid & 1;
        int tok = sp[key];
        const float* basep = qkv + ((size_t)(b * NTOKS + tok)) * H3 + head * HD;
        const float4* ksrc = (const float4*)(basep + DIM + part * 16);
        float* kd = sK + key * 36 + part * 16;
        #pragma unroll
        for (int u = 0; u < 4; u++) {
            float4 kv = ksrc[u];
            kd[u * 4 + 0] = kv.x; kd[u * 4 + 1] = kv.y;
            kd[u * 4 + 2] = kv.z; kd[u * 4 + 3] = kv.w;
        }
        const float4* vsrc = (const float4*)(basep + 2 * DIM + part * 16);
        int d0 = part * 16;
        #pragma unroll
        for (int u = 0; u < 4; u++) {
            float4 vv = vsrc[u];
            sVT[(d0 + u * 4 + 0) * 136 + key] = __float2bfloat16(vv.x);
            sVT[(d0 + u * 4 + 1) * 136 + key] = __float2bfloat16(vv.y);
            sVT[(d0 + u * 4 + 2) * 136 + key] = __float2bfloat16(vv.z);
            sVT[(d0 + u * 4 + 3) * 136 + key] = __float2bfloat16(vv.w);
        }
    }
    __syncthreads();

    for (int kc = 0; kc < 4; kc++) {
        float s[4][4];
        #pragma unroll
        for (int nt = 0; nt < 4; nt++)
            #pragma unroll
            for (int r = 0; r < 4; r++) s[nt][r] = 0.f;
        #pragma unroll
        for (int nt = 0; nt < 4; nt++) {
            int krow = (kc * 32 + nt * 8 + grp) * 36;
            #pragma unroll
            for (int ks = 0; ks < 4; ks++) {
                uint32_t b0 = f2tf(sK[krow + ks * 8 + qid]);
                uint32_t b1 = f2tf(sK[krow + ks * 8 + qid + 4]);
                mma_tf32(s[nt], qa[ks][0], qa[ks][1], qa[ks][2], qa[ks][3], b0, b1);
            }
        }
        float mx0 = fmaxf(fmaxf(s[0][0], s[0][1]), fmaxf(s[1][0], s[1][1]));
        mx0 = fmaxf(mx0, fmaxf(fmaxf(s[2][0], s[2][1]), fmaxf(s[3][0], s[3][1])));
        float mx1 = fmaxf(fmaxf(s[0][2], s[0][3]), fmaxf(s[1][2], s[1][3]));
        mx1 = fmaxf(mx1, fmaxf(fmaxf(s[2][2], s[2][3]), fmaxf(s[3][2], s[3][3])));
        mx0 = fmaxf(mx0, __shfl_xor_sync(0xffffffffu, mx0, 1));
        mx0 = fmaxf(mx0, __shfl_xor_sync(0xffffffffu, mx0, 2));
        mx1 = fmaxf(mx1, __shfl_xor_sync(0xffffffffu, mx1, 1));
        mx1 = fmaxf(mx1, __shfl_xor_sync(0xffffffffu, mx1, 2));
        float mn0 = fmaxf(m0v, mx0), mn1 = fmaxf(m1v, mx1);
        float f0 = fexp(m0v - mn0), f1 = fexp(m1v - mn1);
        m0v = mn0; m1v = mn1;
        l0 *= f0; l1 *= f1;
        #pragma unroll
        for (int nt = 0; nt < 4; nt++) {
            o[nt][0] *= f0; o[nt][1] *= f0;
            o[nt][2] *= f1; o[nt][3] *= f1;
        }
        float ps0 = 0.f, ps1 = 0.f;
        #pragma unroll
        for (int nt = 0; nt < 4; nt++) {
            s[nt][0] = fexp(s[nt][0] - mn0); ps0 += s[nt][0];
            s[nt][1] = fexp(s[nt][1] - mn0); ps0 += s[nt][1];
            s[nt][2] = fexp(s[nt][2] - mn1); ps1 += s[nt][2];
            s[nt][3] = fexp(s[nt][3] - mn1); ps1 += s[nt][3];
        }
        l0 += ps0; l1 += ps1;
        #pragma unroll
        for (int ks = 0; ks < 2; ks++) {
            uint32_t a0 = pkbf(s[2 * ks][0],     s[2 * ks][1]);
            uint32_t a1 = pkbf(s[2 * ks][2],     s[2 * ks][3]);
            uint32_t a2 = pkbf(s[2 * ks + 1][0], s[2 * ks + 1][1]);
            uint32_t a3 = pkbf(s[2 * ks + 1][2], s[2 * ks + 1][3]);
            #pragma unroll
            for (int ntd = 0; ntd < 4; ntd++) {
                int base = (ntd * 8 + grp) * 68 + kc * 16 + ks * 8 + qid;
                mma_bf16(o[ntd], a0, a1, a2, a3, vtw[base], vtw[base + 4]);
            }
        }
    }
    l0 += __shfl_xor_sync(0xffffffffu, l0, 1);
    l0 += __shfl_xor_sync(0xffffffffu, l0, 2);
    l1 += __shfl_xor_sync(0xffffffffu, l1, 1);
    l1 += __shfl_xor_sync(0xffffffffu, l1, 2);
    float inv0 = 1.0f / l0, inv1 = 1.0f / l1;
    float* out0 = ycat + ((size_t)(b * NTOKS + tok0)) * YC + DIM + head * HD;
    float* out1 = ycat + ((size_t)(b * NTOKS + tok1)) * YC + DIM + head * HD;
    #pragma unroll
    for (int nt = 0; nt < 4; nt++) {
        float2 w0; w0.x = o[nt][0] * inv0; w0.y = o[nt][1] * inv0;
        float2 w1; w1.x = o[nt][2] * inv1; w1.y = o[nt][3] * inv1;
        *(float2*)(out0 + nt * 8 + 2 * qid) = w0;
        *(float2*)(out1 + nt * 8 + 2 * qid) = w1;
    }
}

// ---------------- transposed relative position bias ----------------
__global__ void rpbt_kernel(const int* __restrict__ rpi, const float* __restrict__ table,
                            float* __restrict__ rpbT) {
    int idx = blockIdx.x * 256 + threadIdx.x;
    if (idx >= NHEAD * WIN * WIN) return;
    int h = idx >> 16;
    int r = idx & 65535;
    int kj = r >> 8, qi = r & 255;
    rpbT[idx] = table[rpi[qi * WIN + kj] * NHEAD + h];
}

// ---------------- shifted-window attention via MMA ----------------
__global__ void __launch_bounds__(512) winattn_mma_kernel(
    const float* __restrict__ qkv, const float* __restrict__ mask,
    const float* __restrict__ rpbT, float* __restrict__ ycat)
{
    __shared__ __align__(16) char smem_raw[36864];
    float* sQ = (float*)smem_raw;
    float* sK = (float*)smem_raw;
    __nv_bfloat16* sVT = (__nv_bfloat16*)(smem_raw + 18432);
    uint32_t* vtw = (uint32_t*)(smem_raw + 18432);

    int wl = blockIdx.x, head = blockIdx.y, b = blockIdx.z;
    int wy = wl >> 3, wx = wl & 7;
    int tid = threadIdx.x;
    int warp = tid >> 5, lane = tid & 31;
    int grp = lane >> 2, qid = lane & 3;
    int q0 = warp * 16;

    {
        int r = tid >> 1, off = (tid & 1) * 16;
        int i = r >> 4, j = r & 15;
        int n = (((wy * WS + i + SS) & 127) << 7) | ((wx * WS + j + SS) & 127);
        const float4* src = (const float4*)(qkv + ((size_t)(b * NTOKS + n)) * H3
                                            + head * HD + off);
        #pragma unroll
        for (int u = 0; u < 4; u++) {
            float4 v = src[u];
            float* d = sQ + r * 36 + off + u * 4;
            d[0] = v.x * 0.17677669529663687f;
            d[1] = v.y * 0.17677669529663687f;
            d[2] = v.z * 0.17677669529663687f;
            d[3] = v.w * 0.17677669529663687f;
        }
    }
    __syncthreads();

    uint32_t qa[4][4];
    #pragma unroll
    for (int ks = 0; ks < 4; ks++) {
        qa[ks][0] = f2tf(sQ[(q0 + grp    ) * 36 + ks * 8 + qid    ]);
        qa[ks][1] = f2tf(sQ[(q0 + grp + 8) * 36 + ks * 8 + qid    ]);
        qa[ks][2] = f2tf(sQ[(q0 + grp    ) * 36 + ks * 8 + qid + 4]);
        qa[ks][3] = f2tf(sQ[(q0 + grp + 8) * 36 + ks * 8 + qid + 4]);
    }
    int r0 = q0 + grp, r1 = r0 + 8;
    int i0 = r0 >> 4, j0 = r0 & 15;
    int i1 = r1 >> 4, j1 = r1 & 15;
    int tok0 = (((wy * WS + i0 + SS) & 127) << 7) | ((wx * WS + j0 + SS) & 127);
    int tok1 = (((wy * WS + i1 + SS) & 127) << 7) | ((wx * WS + j1 + SS) & 127);
    const float* rpbh  = rpbT + (size_t)head * (WIN * WIN);
    const float* maskw = mask + (size_t)wl * (WIN * WIN);

    float o[4][4];
    #pragma unroll
    for (int nt = 0; nt < 4; nt++)
        #pragma unroll
        for (int r = 0; r < 4; r++) o[nt][r] = 0.f;
    float m0v = -1e30f, m1v = -1e30f, l0 = 0.f, l1 = 0.f;
    __syncthreads();

    for (int kt = 0; kt < 2; kt++) {
        {
            int key = tid >> 2, part = tid & 3;
            int p = kt * 128 + key;
            int pi = p >> 4, pj = p & 15;
            int np = (((wy * WS + pi + SS) & 127) << 7) | ((wx * WS + pj + SS) & 127);
            const float* basep = qkv + ((size_t)(b * NTOKS + np)) * H3 + head * HD;
            const float4* ksrc = (const float4*)(basep + DIM + part * 8);
            float4 k0 = ksrc[0], k1 = ksrc[1];
            float* kd = sK + key * 36 + part * 8;
            kd[0] = k0.x; kd[1] = k0.y; kd[2] = k0.z; kd[3] = k0.w;
            kd[4] = k1.x; kd[5] = k1.y; kd[6] = k1.z; kd[7] = k1.w;
            const float4* vsrc = (const float4*)(basep + 2 * DIM + part * 8);
            float4 v0 = vsrc[0], v1 = vsrc[1];
            int d0 = part * 8;
            sVT[(d0 + 0) * 136 + key] = __float2bfloat16(v0.x);
            sVT[(d0 + 1) * 136 + key] = __float2bfloat16(v0.y);
            sVT[(d0 + 2) * 136 + key] = __float2bfloat16(v0.z);
            sVT[(d0 + 3) * 136 + key] = __float2bfloat16(v0.w);
            sVT[(d0 + 4) * 136 + key] = __float2bfloat16(v1.x);
            sVT[(d0 + 5) * 136 + key] = __float2bfloat16(v1.y);
            sVT[(d0 + 6) * 136 + key] = __float2bfloat16(v1.z);
            sVT[(d0 + 7) * 136 + key] = __float2bfloat16(v1.w);
        }
        __syncthreads();

        for (int kc = 0; kc < 4; kc++) {
            int kbase = kt * 128 + kc * 32;
            float s[4][4];
            #pragma unroll
            for (int nt = 0; nt < 4; nt++)
                #pragma unroll
                for (int r = 0; r < 4; r++) s[nt][r] = 0.f;
            #pragma unroll
            for (int nt = 0; nt < 4; nt++) {
                int krow = (kc * 32 + nt * 8 + grp) * 36;
                #pragma unroll
                for (int ks = 0; ks < 4; ks++) {
                    uint32_t b0 = f2tf(sK[krow + ks * 8 + qid]);
                    uint32_t b1 = f2tf(sK[krow + ks * 8 + qid + 4]);
                    mma_tf32(s[nt], qa[ks][0], qa[ks][1], qa[ks][2], qa[ks][3], b0, b1);
                }
            }
            #pragma unroll
            for (int nt = 0; nt < 4; nt++) {
                int c0 = kbase + nt * 8 + 2 * qid;
                s[nt][0] += rpbh[c0 * WIN + r0] + maskw[c0 * WIN + r0];
                s[nt][1] += rpbh[(c0 + 1) * WIN + r0] + maskw[(c0 + 1) * WIN + r0];
                s[nt][2] += rpbh[c0 * WIN + r1] + maskw[c0 * WIN + r1];
                s[nt][3] += rpbh[(c0 + 1) * WIN + r1] + maskw[(c0 + 1) * WIN + r1];
            }
            float mx0 = fmaxf(fmaxf(s[0][0], s[0][1]), fmaxf(s[1][0], s[1][1]));
            mx0 = fmaxf(mx0, fmaxf(fmaxf(s[2][0], s[2][1]), fmaxf(s[3][0], s[3][1])));
            float mx1 = fmaxf(fmaxf(s[0][2], s[0][3]), fmaxf(s[1][2], s[1][3]));
            mx1 = fmaxf(mx1, fmaxf(fmaxf(s[2][2], s[2][3]), fmaxf(s[3][2], s[3][3])));
            mx0 = fmaxf(mx0, __shfl_xor_sync(0xffffffffu, mx0, 1));
            mx0 = fmaxf(mx0, __shfl_xor_sync(0xffffffffu, mx0, 2));
            mx1 = fmaxf(mx1, __shfl_xor_sync(0xffffffffu, mx1, 1));
            mx1 = fmaxf(mx1, __shfl_xor_sync(0xffffffffu, mx1, 2));
            float mn0 = fmaxf(m0v, mx0), mn1 = fmaxf(m1v, mx1);
            float f0 = fexp(m0v - mn0), f1 = fexp(m1v - mn1);
            m0v = mn0; m1v = mn1;
            l0 *= f0; l1 *= f1;
            #pragma unroll
            for (int nt = 0; nt < 4; nt++) {
                o[nt][0] *= f0; o[nt][1] *= f0;
                o[nt][2] *= f1; o[nt][3] *= f1;
            }
            float ps0 = 0.f, ps1 = 0.f;
            #pragma unroll
            for (int nt = 0; nt < 4; nt++) {
                s[nt][0] = fexp(s[nt][0] - mn0); ps0 += s[nt][0];
                s[nt][1] = fexp(s[nt][1] - mn0); ps0 += s[nt][1];
                s[nt][2] = fexp(s[nt][2] - mn1); ps1 += s[nt][2];
                s[nt][3] = fexp(s[nt][3] - mn1); ps1 += s[nt][3];
            }
            l0 += ps0; l1 += ps1;
            #pragma unroll
            for (int ks = 0; ks < 2; ks++) {
                uint32_t a0 = pkbf(s[2 * ks][0],     s[2 * ks][1]);
                uint32_t a1 = pkbf(s[2 * ks][2],     s[2 * ks][3]);
                uint32_t a2 = pkbf(s[2 * ks + 1][0], s[2 * ks + 1][1]);
                uint32_t a3 = pkbf(s[2 * ks + 1][2], s[2 * ks + 1][3]);
                #pragma unroll
                for (int ntd = 0; ntd < 4; ntd++) {
                    int base = (ntd * 8 + grp) * 68 + kc * 16 + ks * 8 + qid;
                    mma_bf16(o[ntd], a0, a1, a2, a3, vtw[base], vtw[base + 4]);
                }
            }
        }
        __syncthreads();
    }
    l0 += __shfl_xor_sync(0xffffffffu, l0, 1);
    l0 += __shfl_xor_sync(0xffffffffu, l0, 2);
    l1 += __shfl_xor_sync(0xffffffffu, l1, 1);
    l1 += __shfl_xor_sync(0xffffffffu, l1, 2);
    float inv0 = 1.0f / l0, inv1 = 1.0f / l1;
    float* out0 = ycat + ((size_t)(b * NTOKS + tok0)) * YC + head * HD;
    float* out1 = ycat + ((size_t)(b * NTOKS + tok1)) * YC + head * HD;
    #pragma unroll
    for (int nt = 0; nt < 4; nt++) {
        float2 w0; w0.x = o[nt][0] * inv0; w0.y = o[nt][1] * inv0;
        float2 w1; w1.x = o[nt][2] * inv1; w1.y = o[nt][3] * inv1;
        *(float2*)(out0 + nt * 8 + 2 * qid) = w0;
        *(float2*)(out1 + nt * 8 + 2 * qid) = w1;
    }
}

// ---------------- pack merged projection ----------------
__global__ void packproj_kernel(const float* __restrict__ ww, const float* __restrict__ wa,
                                const float* __restrict__ bw, const float* __restrict__ ba,
                                float* __restrict__ Bcat, float* __restrict__ bcat) {
    int idx = blockIdx.x * 256 + threadIdx.x;
    if (idx >= YC * DIM) return;
    int k = idx / DIM, n = idx % DIM;
    Bcat[idx] = (k < DIM) ? ww[k * DIM + n] : wa[(k - DIM) * DIM + n];
    if (idx < DIM) bcat[idx] = bw[idx] + ba[idx];
}

// ---------------- gather token-dict features (float4) ----------------
__global__ void gather_td_kernel(const float* __restrict__ tdf, const int* __restrict__ tkid,
                                 float* __restrict__ xc) {
    int idx = blockIdx.x * 256 + threadIdx.x;
    if (idx >= TOT * (DTD / 4)) return;
    int tok = idx >> 4, j = idx & 15;
    int b = tok >> 14;
    const float4* src = (const float4*)tdf;
    float4* dst = (float4*)xc;
    dst[(size_t)tok * (CH / 4) + (MLPH / 4) + j] =
        src[((size_t)(b << 6) + tkid[tok]) * (DTD / 4) + j];
}

// ---------------- depthwise 5x5 conv: 2 channels x 4 y-outputs per thread ----------
__global__ void dwconv_kernel(const float* __restrict__ xc, const float* __restrict__ w,
                              const float* __restrict__ bias, float* __restrict__ sout) {
    int u = blockIdx.x * 256 + threadIdx.x;
    if (u >= TOT * CH / 8) return;
    int cp = u % (CH / 2);
    int c = cp * 2;
    int p4 = u / (CH / 2);
    int x = p4 & 127, y4 = (p4 >> 7) & 31, b = p4 >> 12;
    int y0 = y4 << 2;
    float2 wr[25];
    #pragma unroll
    for (int i = 0; i < 25; i++) wr[i] = *(const float2*)(w + i * CH + c);
    float2 acc[4];
    #pragma unroll
    for (int r = 0; r < 4; r++) { acc[r].x = 0.f; acc[r].y = 0.f; }
    #pragma unroll
    for (int ry = 0; ry < 8; ry++) {
        int yy = y0 + ry - 2;
        if ((unsigned)yy >= 128u) continue;
        #pragma unroll
        for (int dx = 0; dx < 5; dx++) {
            int xx = x + dx - 2;
            if ((unsigned)xx >= 128u) continue;
            float2 v = *(const float2*)(xc + (size_t)((b << 14) | (yy << 7) | xx) * CH + c);
            #pragma unroll
            for (int r = 0; r < 4; r++) {
                int dy = ry - r;
                if (dy >= 0 && dy < 5) {
                    float2 ww2 = wr[dy * 5 + dx];
                    acc[r].x = fmaf(v.x, ww2.x, acc[r].x);
                    acc[r].y = fmaf(v.y, ww2.y, acc[r].y);
                }
            }
        }
    }
    float2 bc = *(const float2*)(bias + c);
    #pragma unroll
    for (int r = 0; r < 4; r++) {
        size_t idx = (size_t)((b << 14) | ((y0 + r) << 7) | x) * CH + c;
        float2 xv = *(const float2*)(xc + idx);
        float2 ov;
        ov.x = xv.x + gelu_f(acc[r].x + bc.x);
        ov.y = xv.y + gelu_f(acc[r].y + bc.y);
        *(float2*)(sout + idx) = ov;
    }
}

// ---------------- host side ----------------
static void sgemm(int epi, const float* A, const float* B, const float* bias, const float* D,
                  float* C, int M, int N, int K, int ldc, int ldd,
                  int nz = 1, size_t sA = 0, size_t sB = 0, size_t sD = 0, size_t sC = 0) {
    dim3 grid(N / 64, M / 128, nz), block(256);
    if (epi == 0)      tgemm_k<0><<<grid, block>>>(A, B, bias, D, C, M, N, K, ldc, ldd, sA, sB, sD, sC);
    else if (epi == 1) tgemm_k<1><<<grid, block>>>(A, B, bias, D, C, M, N, K, ldc, ldd, sA, sB, sD, sC);
    else               tgemm_k<2><<<grid, block>>>(A, B, bias, D, C, M, N, K, ldc, ldd, sA, sB, sD, sC);
}

extern "C" void kernel_launch(void* const* d_in, const int* in_sizes, int n_in,
                              void* d_out, int out_size) {
    (void)in_sizes; (void)out_size;
    const float* x         = (const float*)d_in[0];
    const float* td        = (const float*)d_in[1];
    const float* attn_mask = (const float*)d_in[2];
    const int*   rpi       = (const int*)  d_in[3];
    int base = (n_in >= 32) ? 6 : 4;
    const float* norm1_g    = (const float*)d_in[base + 0];
    const float* norm1_b    = (const float*)d_in[base + 1];
    const float* norm2_g    = (const float*)d_in[base + 2];
    const float* norm2_b    = (const float*)d_in[base + 3];
    const float* wqkv_w     = (const float*)d_in[base + 4];
    const float* wqkv_b     = (const float*)d_in[base + 5];
    const float* wq_w       = (const float*)d_in[base + 6];
    const float* wq_b       = (const float*)d_in[base + 7];
    const float* wk_w       = (const float*)d_in[base + 8];
    const float* wk_b       = (const float*)d_in[base + 9];
    const float* wv_w       = (const float*)d_in[base + 10];
    const float* wv_b       = (const float*)d_in[base + 11];
    const float* atd_scale  = (const float*)d_in[base + 12];
    const float* aca_proj_w = (const float*)d_in[base + 13];
    const float* aca_proj_b = (const float*)d_in[base + 14];
    const float* rpb_table  = (const float*)d_in[base + 15];
    const float* win_proj_w = (const float*)d_in[base + 16];
    const float* win_proj_b = (const float*)d_in[base + 17];
    const float* fc_td_w    = (const float*)d_in[base + 18];
    const float* fc_td_b    = (const float*)d_in[base + 19];
    const float* fc1_w      = (const float*)d_in[base + 20];
    const float* fc1_b      = (const float*)d_in[base + 21];
    const float* dw_w       = (const float*)d_in[base + 22];
    const float* dw_b       = (const float*)d_in[base + 23];
    const float* fc2_w      = (const float*)d_in[base + 24];
    const float* fc2_b      = (const float*)d_in[base + 25];

    float *xn, *qkv, *qb, *kn, *vb, *tdf, *sim, *ycat, *xs, *rpbT, *xc, *sb, *bcat, *bcatb;
    int *tkid, *sidx, *off;
    cudaGetSymbolAddress((void**)&xn,    g_xn);
    cudaGetSymbolAddress((void**)&qkv,   g_qkv);
    cudaGetSymbolAddress((void**)&qb,    g_q);
    cudaGetSymbolAddress((void**)&kn,    g_kn);
    cudaGetSymbolAddress((void**)&vb,    g_v);
    cudaGetSymbolAddress((void**)&tdf,   g_tdf);
    cudaGetSymbolAddress((void**)&sim,   g_sim);
    cudaGetSymbolAddress((void**)&tkid,  g_tkid);
    cudaGetSymbolAddress((void**)&sidx,  g_sidx);
    cudaGetSymbolAddress((void**)&off,   g_off);
    cudaGetSymbolAddress((void**)&ycat,  g_ycat);
    cudaGetSymbolAddress((void**)&xs,    g_xs);
    cudaGetSymbolAddress((void**)&rpbT,  g_rpbT);
    cudaGetSymbolAddress((void**)&xc,    g_xc);
    cudaGetSymbolAddress((void**)&sb,    g_s);
    cudaGetSymbolAddress((void**)&bcat,  g_bcat);
    cudaGetSymbolAddress((void**)&bcatb, g_bcatb);

    bool fork = (g_s2 != nullptr && g_ev1 != nullptr && g_ev2 != nullptr);

    // 1) LN1 + qkv GEMM on main stream
    ln_kernel<<<TOT / 8, 256>>>(x, norm1_g, norm1_b, xn);
    sgemm(0, xn, wqkv_w, wqkv_b, nullptr, qkv, TOT, H3, DIM, H3, 0);

    if (fork) {
        cudaEventRecord(g_ev1, 0);
        cudaStreamWaitEvent(g_s2, g_ev1, 0);
        packproj_kernel<<<(YC * DIM + 255) / 256, 256, 0, g_s2>>>(
            win_proj_w, aca_proj_w, win_proj_b, aca_proj_b, bcat, bcatb);
        rpbt_kernel<<<(NHEAD * WIN * WIN + 255) / 256, 256, 0, g_s2>>>(rpi, rpb_table, rpbT);
        winattn_mma_kernel<<<dim3(NWIN, NHEAD, BATCH), 512, 0, g_s2>>>(
            qkv, attn_mask, rpbT, ycat);
        cudaEventRecord(g_ev2, g_s2);
    }

    // main stream: ATD chain
    qproj_kernel<<<(TOT * RD + 255) / 256, 256>>>(xn, wq_w, wq_b, qb);
    tdprep_kernel<<<BATCH * NDICT, DIM>>>(td, wk_w, wk_b, wv_w, wv_b, fc_td_w, fc_td_b,
                                          kn, vb, tdf);
    atd_kernel<<<TOT, NDICT>>>(qb, kn, atd_scale, sim, tkid);
    sgemm(2, sim, vb, nullptr, x, xs, NTOKS, DIM, NDICT, DIM, DIM,
          BATCH, (size_t)NTOKS * NDICT, (size_t)NDICT * DIM,
          (size_t)NTOKS * DIM, (size_t)NTOKS * DIM);
    hist_kernel<<<BATCH, 256>>>(tkid, off);
    scatter_kernel<<<BATCH * NDICT, 256>>>(tkid, off, sidx);
    acmsa_mma_kernel<<<dim3(NG, NHEAD, BATCH), 256>>>(qkv, sidx, ycat);

    if (fork) {
        cudaStreamWaitEvent(0, g_ev2, 0);   // join
    } else {
        packproj_kernel<<<(YC * DIM + 255) / 256, 256>>>(win_proj_w, aca_proj_w,
                                                         win_proj_b, aca_proj_b, bcat, bcatb);
        rpbt_kernel<<<(NHEAD * WIN * WIN + 255) / 256, 256>>>(rpi, rpb_table, rpbT);
        winattn_mma_kernel<<<dim3(NWIN, NHEAD, BATCH), 512>>>(qkv, attn_mask, rpbT, ycat);
    }

    // merged projection + FFN tail
    sgemm(2, ycat, bcat, bcatb, xs, xs, TOT, DIM, YC, DIM, DIM);
    ln_kernel<<<TOT / 8, 256>>>(xs, norm2_g, norm2_b, xn);
    sgemm(1, xn, fc1_w, fc1_b, nullptr, xc, TOT, MLPH, DIM, CH, 0);
    gather_td_kernel<<<(TOT * (DTD / 4) + 255) / 256, 256>>>(tdf, tkid, xc);
    dwconv_kernel<<<(TOT * CH / 8 + 255) / 256, 256>>>(xc, dw_w, dw_b, sb);
    sgemm(2, sb, fc2_w, fc2_b, xs, (float*)d_out, TOT, DIM, CH, DIM, DIM);
}

// round 16
// speedup vs baseline: 1.2067x; 1.0006x over previous
#include <cuda_runtime.h>
#include <cuda_bf16.h>
#include <cstdint>
#include <math.h>

// ---------------- problem constants ----------------
#define BATCH 4
#define IMGH 128
#define IMGW 128
#define NTOKS (IMGH*IMGW)
#define TOT (BATCH*NTOKS)
#define DIM 192
#define H3 576
#define NHEAD 6
#define HD 32
#define WS 16
#define SS 8
#define NWIN 64
#define WIN 256
#define NDICT 64
#define RD 10
#define DTD 64
#define MLPH 384
#define CH 448
#define GS 128
#define NG 128
#define YC 384

// ---------------- scratch ----------------
__device__ __align__(16) float g_xn  [TOT*DIM];
__device__ __align__(16) float g_qkv [TOT*H3];
__device__ __align__(16) float g_q   [TOT*RD];
__device__ __align__(16) float g_kn  [BATCH*NDICT*RD];
__device__ __align__(16) float g_v   [BATCH*NDICT*DIM];
__device__ __align__(16) float g_tdf [BATCH*NDICT*DTD];
__device__ __align__(16) float g_sim [TOT*NDICT];
__device__           int   g_tkid[TOT];
__device__           int   g_sidx[TOT];
__device__           int   g_off [BATCH*NDICT];
__device__ __align__(16) float g_ycat[TOT*YC];
__device__ __align__(16) float g_xs  [TOT*DIM];
__device__ __align__(16) float g_rpbT[NHEAD*WIN*WIN];
__device__ __align__(16) float g_xc  [TOT*CH];
__device__ __align__(16) float g_s   [TOT*CH];
__device__ __align__(16) float g_bcat[YC*DIM];
__device__ __align__(16) float g_bcatb[DIM];

// ---------------- side stream for fork/join ----------------
static cudaStream_t g_s2 = nullptr;
static cudaEvent_t g_ev1 = nullptr, g_ev2 = nullptr;
namespace {
struct StreamInit {
    StreamInit() {
        if (cudaStreamCreateWithFlags(&g_s2, cudaStreamNonBlocking) != cudaSuccess) g_s2 = nullptr;
        if (cudaEventCreateWithFlags(&g_ev1, cudaEventDisableTiming) != cudaSuccess) g_ev1 = nullptr;
        if (cudaEventCreateWithFlags(&g_ev2, cudaEventDisableTiming) != cudaSuccess) g_ev2 = nullptr;
    }
};
StreamInit g_stream_init;
}

// ---------------- device helpers ----------------
__device__ __forceinline__ float fexp(float x) {
    x = fmaxf(x, -80.0f);
    float t = x * 1.4426950408889634f;
    float r = rintf(t);
    float f = t - r;
    float p = 1.3333558146e-3f;
    p = fmaf(p, f, 9.6181291076e-3f);
    p = fmaf(p, f, 5.5504108665e-2f);
    p = fmaf(p, f, 2.4022650696e-1f);
    p = fmaf(p, f, 6.9314718056e-1f);
    p = fmaf(p, f, 1.0f);
    int e = (int)r;
    return p * __int_as_float((e + 127) << 23);
}

__device__ __forceinline__ float gelu_f(float v) {
    return 0.5f * v * (1.0f + erff(v * 0.7071067811865476f));
}

__device__ __forceinline__ uint32_t f2tf(float x) {
    uint32_t r;
    asm("cvt.rna.tf32.f32 %0, %1;" : "=r"(r) : "f"(x));
    return r;
}

__device__ __forceinline__ uint32_t pkbf(float lo, float hi) {
    uint32_t r;
    asm("cvt.rn.bf16x2.f32 %0, %1, %2;" : "=r"(r) : "f"(hi), "f"(lo));
    return r;
}

__device__ __forceinline__ void mma_tf32(float c[4],
    uint32_t a0, uint32_t a1, uint32_t a2, uint32_t a3,
    uint32_t b0, uint32_t b1)
{
    asm volatile(
        "mma.sync.aligned.m16n8k8.row.col.f32.tf32.tf32.f32 "
        "{%0,%1,%2,%3}, {%4,%5,%6,%7}, {%8,%9}, {%0,%1,%2,%3};"
        : "+f"(c[0]), "+f"(c[1]), "+f"(c[2]), "+f"(c[3])
        : "r"(a0), "r"(a1), "r"(a2), "r"(a3), "r"(b0), "r"(b1));
}

__device__ __forceinline__ void mma_bf16(float c[4],
    uint32_t a0, uint32_t a1, uint32_t a2, uint32_t a3,
    uint32_t b0, uint32_t b1)
{
    asm volatile(
        "mma.sync.aligned.m16n8k16.row.col.f32.bf16.bf16.f32 "
        "{%0,%1,%2,%3}, {%4,%5,%6,%7}, {%8,%9}, {%0,%1,%2,%3};"
        : "+f"(c[0]), "+f"(c[1]), "+f"(c[2]), "+f"(c[3])
        : "r"(a0), "r"(a1), "r"(a2), "r"(a3), "r"(b0), "r"(b1));
}

__device__ __forceinline__ void cpa16(void* smem_dst, const void* gsrc) {
    uint32_t s = (uint32_t)__cvta_generic_to_shared(smem_dst);
    asm volatile("cp.async.cg.shared.global [%0], [%1], 16;" :: "r"(s), "l"(gsrc));
}

// ---------------- LayerNorm: warp per token, float4, shuffle-only reduce ----------
__global__ void ln_kernel(const float* __restrict__ x, const float* __restrict__ gamma,
                          const float* __restrict__ beta, float* __restrict__ out) {
    int token = blockIdx.x * 8 + (threadIdx.x >> 5);
    int lane = threadIdx.x & 31;
    const float4* xr = (const float4*)(x + (size_t)token * DIM);
    float4 v1 = xr[lane];
    float4 v2 = make_float4(0.f, 0.f, 0.f, 0.f);
    bool has2 = lane < 16;
    if (has2) v2 = xr[32 + lane];
    float s  = (v1.x + v1.y) + (v1.z + v1.w) + (v2.x + v2.y) + (v2.z + v2.w);
    float s2 = v1.x * v1.x + v1.y * v1.y + v1.z * v1.z + v1.w * v1.w
             + v2.x * v2.x + v2.y * v2.y + v2.z * v2.z + v2.w * v2.w;
    #pragma unroll
    for (int o = 16; o > 0; o >>= 1) {
        s  += __shfl_xor_sync(0xffffffffu, s,  o);
        s2 += __shfl_xor_sync(0xffffffffu, s2, o);
    }
    float mu  = s * (1.0f / DIM);
    float var = s2 * (1.0f / DIM) - mu * mu;
    float inv = rsqrtf(var + 1e-5f);
    const float4* g4 = (const float4*)gamma;
    const float4* b4 = (const float4*)beta;
    float4* o4 = (float4*)(out + (size_t)token * DIM);
    {
        float4 gg = g4[lane], bb = b4[lane], ov;
        ov.x = (v1.x - mu) * inv * gg.x + bb.x;
        ov.y = (v1.y - mu) * inv * gg.y + bb.y;
        ov.z = (v1.z - mu) * inv * gg.z + bb.z;
        ov.w = (v1.w - mu) * inv * gg.w + bb.w;
        o4[lane] = ov;
    }
    if (has2) {
        float4 gg = g4[32 + lane], bb = b4[32 + lane], ov;
        ov.x = (v2.x - mu) * inv * gg.x + bb.x;
        ov.y = (v2.y - mu) * inv * gg.y + bb.y;
        ov.z = (v2.z - mu) * inv * gg.z + bb.z;
        ov.w = (v2.w - mu) * inv * gg.w + bb.w;
        o4[32 + lane] = ov;
    }
}

// ---------------- tensor-core GEMM: 128x64x16, 3-stage cp.async, ONE barrier/tile --
template <int EPI>
__global__ void __launch_bounds__(256) tgemm_k(
    const float* __restrict__ A, const float* __restrict__ B,
    const float* __restrict__ bias, const float* __restrict__ D,
    float* __restrict__ C, int M, int N, int K, int ldc, int ldd,
    size_t sA, size_t sB, size_t sD, size_t sC)
{
    __shared__ float As[3][128][20];
    __shared__ float Bs[3][16][72];
    int tid = threadIdx.x;
    int row0 = blockIdx.y * 128, col0 = blockIdx.x * 64;
    int z = blockIdx.z;
    int warp = tid >> 5, lane = tid & 31;
    int wm = (warp >> 1) * 32, wn = (warp & 1) * 32;
    int grp = lane >> 2, qid = lane & 3;

    int ar = tid >> 2, aseg = (tid & 3) << 2;
    int br = tid >> 4, bseg = (tid & 15) << 2;

    const float* Ap = A + (size_t)z * sA + (size_t)row0 * K;
    const float* Bp = B + (size_t)z * sB + col0;
    const float* Dp = D + (size_t)z * sD;
    float*       Cp = C + (size_t)z * sC;

    float acc[2][4][4];
    #pragma unroll
    for (int i = 0; i < 2; i++)
        #pragma unroll
        for (int j = 0; j < 4; j++)
            #pragma unroll
            for (int r = 0; r < 4; r++) acc[i][j][r] = 0.f;

    int T = K >> 4;

    #define PREFETCH(k0, bufi) do { \
        cpa16(&As[bufi][ar][aseg],      Ap + (size_t)ar * K + (k0) + aseg); \
        cpa16(&As[bufi][ar + 64][aseg], Ap + (size_t)(ar + 64) * K + (k0) + aseg); \
        cpa16(&Bs[bufi][br][bseg],      Bp + (size_t)((k0) + br) * N + bseg); \
        asm volatile("cp.async.commit_group;"); } while (0)

    PREFETCH(0, 0);
    PREFETCH(16, 1);
    for (int t = 0; t < T; t++) {
        if (t + 1 < T) asm volatile("cp.async.wait_group 1;");
        else           asm volatile("cp.async.wait_group 0;");
        __syncthreads();   // single barrier: also orders iter t-1 reads vs t+2 prefetch
        if (t + 2 < T) PREFETCH((t + 2) << 4, (t + 2) % 3);
        int buf = t % 3;
        #pragma unroll
        for (int ks = 0; ks < 2; ks++) {
            int kb = ks * 8;
            uint32_t af[2][4], bf[4][2];
            #pragma unroll
            for (int i = 0; i < 2; i++) {
                int m0 = wm + i * 16;
                af[i][0] = f2tf(As[buf][m0 + grp    ][kb + qid    ]);
                af[i][1] = f2tf(As[buf][m0 + grp + 8][kb + qid    ]);
                af[i][2] = f2tf(As[buf][m0 + grp    ][kb + qid + 4]);
                af[i][3] = f2tf(As[buf][m0 + grp + 8][kb + qid + 4]);
            }
            #pragma unroll
            for (int j = 0; j < 4; j++) {
                int n0 = wn + j * 8;
                bf[j][0] = f2tf(Bs[buf][kb + qid    ][n0 + grp]);
                bf[j][1] = f2tf(Bs[buf][kb + qid + 4][n0 + grp]);
            }
            #pragma unroll
            for (int i = 0; i < 2; i++)
                #pragma unroll
                for (int j = 0; j < 4; j++)
                    mma_tf32(acc[i][j], af[i][0], af[i][1], af[i][2], af[i][3],
                             bf[j][0], bf[j][1]);
        }
    }
    #undef PREFETCH

    #pragma unroll
    for (int i = 0; i < 2; i++) {
        #pragma unroll
        for (int hh = 0; hh < 2; hh++) {
            int r = row0 + wm + i * 16 + grp + hh * 8;
            #pragma unroll
            for (int j = 0; j < 4; j++) {
                int cl = col0 + wn + j * 8 + qid * 2;
                float v0 = acc[i][j][hh * 2 + 0];
                float v1 = acc[i][j][hh * 2 + 1];
                if (bias) { float2 bb = *(const float2*)(bias + cl); v0 += bb.x; v1 += bb.y; }
                if (EPI == 1) { v0 = gelu_f(v0); v1 = gelu_f(v1); }
                if (EPI == 2) {
                    float2 dd = *(const float2*)(Dp + (size_t)r * ldd + cl);
                    v0 += dd.x; v1 += dd.y;
                }
                float2 ov; ov.x = v0; ov.y = v1;
                *(float2*)(Cp + (size_t)r * ldc + cl) = ov;
            }
        }
    }
}

// ---------------- q projection (float4 xn loads) ----------------
__global__ void qproj_kernel(const float* __restrict__ xn, const float* __restrict__ wq,
                             const float* __restrict__ bq, float* __restrict__ q) {
    int idx = blockIdx.x * 256 + threadIdx.x;
    if (idx >= TOT * RD) return;
    int tok = idx / RD, j = idx % RD;
    const float4* x4 = (const float4*)(xn + (size_t)tok * DIM);
    float s0 = 0.f, s1 = 0.f, s2 = 0.f, s3 = 0.f;
    #pragma unroll 8
    for (int k4 = 0; k4 < DIM / 4; k4++) {
        float4 v = x4[k4];
        int k = k4 * 4;
        s0 = fmaf(v.x, wq[(k + 0) * RD + j], s0);
        s1 = fmaf(v.y, wq[(k + 1) * RD + j], s1);
        s2 = fmaf(v.z, wq[(k + 2) * RD + j], s2);
        s3 = fmaf(v.w, wq[(k + 3) * RD + j], s3);
    }
    q[idx] = bq[j] + (s0 + s1) + (s2 + s3);
}

// ---------------- dictionary prep ----------------
__global__ void tdprep_kernel(const float* __restrict__ td,
                              const float* __restrict__ wk, const float* __restrict__ bk,
                              const float* __restrict__ wv, const float* __restrict__ bv,
                              const float* __restrict__ wtd, const float* __restrict__ btd,
                              float* __restrict__ kn, float* __restrict__ vout,
                              float* __restrict__ tdf) {
    int bm = blockIdx.x;
    int t = threadIdx.x;
    __shared__ float tr[DIM];
    __shared__ float kr[RD];
    __shared__ float sinv;
    tr[t] = td[(size_t)bm * DIM + t];
    __syncthreads();
    if (t < RD) {
        float s0 = 0.f, s1 = 0.f, s2 = 0.f, s3 = 0.f;
        #pragma unroll 4
        for (int k = 0; k < DIM; k += 4) {
            s0 = fmaf(tr[k + 0], wk[(k + 0) * RD + t], s0);
            s1 = fmaf(tr[k + 1], wk[(k + 1) * RD + t], s1);
            s2 = fmaf(tr[k + 2], wk[(k + 2) * RD + t], s2);
            s3 = fmaf(tr[k + 3], wk[(k + 3) * RD + t], s3);
        }
        kr[t] = bk[t] + (s0 + s1) + (s2 + s3);
    }
    {
        float s0 = 0.f, s1 = 0.f, s2 = 0.f, s3 = 0.f;
        #pragma unroll 4
        for (int k = 0; k < DIM; k += 4) {
            s0 = fmaf(tr[k + 0], wv[(k + 0) * DIM + t], s0);
            s1 = fmaf(tr[k + 1], wv[(k + 1) * DIM + t], s1);
            s2 = fmaf(tr[k + 2], wv[(k + 2) * DIM + t], s2);
            s3 = fmaf(tr[k + 3], wv[(k + 3) * DIM + t], s3);
        }
        vout[(size_t)bm * DIM + t] = bv[t] + (s0 + s1) + (s2 + s3);
    }
    if (t < DTD) {
        float s0 = 0.f, s1 = 0.f, s2 = 0.f, s3 = 0.f;
        #pragma unroll 4
        for (int k = 0; k < DIM; k += 4) {
            s0 = fmaf(tr[k + 0], wtd[(k + 0) * DTD + t], s0);
            s1 = fmaf(tr[k + 1], wtd[(k + 1) * DTD + t], s1);
            s2 = fmaf(tr[k + 2], wtd[(k + 2) * DTD + t], s2);
            s3 = fmaf(tr[k + 3], wtd[(k + 3) * DTD + t], s3);
        }
        tdf[(size_t)bm * DTD + t] = btd[t] + (s0 + s1) + (s2 + s3);
    }
    __syncthreads();
    if (t == 0) {
        float n = 0.f;
        for (int i = 0; i < RD; i++) n += kr[i] * kr[i];
        sinv = 1.0f / fmaxf(sqrtf(n), 1e-12f);
    }
    __syncthreads();
    if (t < RD) kn[bm * RD + t] = kr[t] * sinv;
}

// ---------------- ATD cross-attn ----------------
__global__ void atd_kernel(const float* __restrict__ q, const float* __restrict__ kn,
                           const float* __restrict__ scale_p,
                           float* __restrict__ sim, int* __restrict__ tkid) {
    int tok = blockIdx.x;
    int b = tok >> 14;
    int t = threadIdx.x;
    int w = t >> 5, lane = t & 31;
    __shared__ float qn[RD];
    __shared__ float wmax[2]; __shared__ int widx[2];
    __shared__ float wsum[2];
    __shared__ float red0, red1;
    if (t == 0) {
        float qq[RD]; float n = 0.f;
        #pragma unroll
        for (int i = 0; i < RD; i++) { qq[i] = q[(size_t)tok * RD + i]; n += qq[i] * qq[i]; }
        float inv = 1.0f / fmaxf(sqrtf(n), 1e-12f);
        #pragma unroll
        for (int i = 0; i < RD; i++) qn[i] = qq[i] * inv;
    }
    __syncthreads();
    float sc = 1.0f + fminf(fmaxf(scale_p[0], 0.0f), 3.0f) * 4.1588830833596715f;
    const float* kr = kn + ((size_t)b * NDICT + t) * RD;
    float s = 0.f;
    #pragma unroll
    for (int i = 0; i < RD; i++) s = fmaf(qn[i], kr[i], s);
    float sv = s * sc;

    float mv = sv; int mi = t;
    #pragma unroll
    for (int o = 16; o > 0; o >>= 1) {
        float ov = __shfl_down_sync(0xffffffffu, mv, o);
        int   oi = __shfl_down_sync(0xffffffffu, mi, o);
        if (ov > mv || (ov == mv && oi < mi)) { mv = ov; mi = oi; }
    }
    if (lane == 0) { wmax[w] = mv; widx[w] = mi; }
    __syncthreads();
    if (t == 0) {
        float m0 = wmax[0], m1 = wmax[1];
        int am = (m1 > m0) ? widx[1] : widx[0];
        red0 = fmaxf(m0, m1);
        tkid[tok] = am;
    }
    __syncthreads();
    float e = fexp(sv - red0);
    float es = e;
    #pragma unroll
    for (int o = 16; o > 0; o >>= 1) es += __shfl_down_sync(0xffffffffu, es, o);
    if (lane == 0) wsum[w] = es;
    __syncthreads();
    if (t == 0) red1 = 1.0f / (wsum[0] + wsum[1]);
    __syncthreads();
    sim[(size_t)tok * NDICT + t] = e * red1;
}

// ---------------- stable counting sort ----------------
__global__ void hist_kernel(const int* __restrict__ tkid, int* __restrict__ off) {
    int b = blockIdx.x;
    __shared__ int h[NDICT];
    int t = threadIdx.x;
    if (t < NDICT) h[t] = 0;
    __syncthreads();
    for (int i = t; i < NTOKS; i += 256) atomicAdd(&h[tkid[b * NTOKS + i]], 1);
    __syncthreads();
    if (t == 0) {
        int acc = 0;
        for (int k = 0; k < NDICT; k++) { off[b * NDICT + k] = acc; acc += h[k]; }
    }
}

// int4 ballot scatter: thread handles tokens 4t..4t+3; stable order proven by
// 4l'+j' < 4l+j  <=>  l'<l or (l'==l and j'<j).
__global__ void scatter_kernel(const int* __restrict__ tkid, const int* __restrict__ off,
                               int* __restrict__ sidx) {
    int b = blockIdx.x >> 6, key = blockIdx.x & 63;
    const int4* ids4 = (const int4*)(tkid + b * NTOKS);
    int base = off[b * NDICT + key];
    int t = threadIdx.x, lane = t & 31, w = t >> 5;
    __shared__ int wc[8];
    for (int c4 = 0; c4 < NTOKS / 4; c4 += 256) {
        int4 id = ids4[c4 + t];
        bool f0 = (id.x == key), f1 = (id.y == key), f2 = (id.z == key), f3 = (id.w == key);
        unsigned m0 = __ballot_sync(0xffffffffu, f0);
        unsigned m1 = __ballot_sync(0xffffffffu, f1);
        unsigned m2 = __ballot_sync(0xffffffffu, f2);
        unsigned m3 = __ballot_sync(0xffffffffu, f3);
        int wtot = __popc(m0) + __popc(m1) + __popc(m2) + __popc(m3);
        if (lane == 0) wc[w] = wtot;
        __syncthreads();
        int pre = 0, tot = 0;
        #pragma unroll
        for (int i = 0; i < 8; i++) { int cnt = wc[i]; tot += cnt; if (i < w) pre += cnt; }
        unsigned below = (1u << lane) - 1;
        int prelane = __popc(m0 & below) + __popc(m1 & below)
                    + __popc(m2 & below) + __popc(m3 & below);
        int tok0 = (c4 + t) * 4;
        int p = base + pre + prelane;
        if (f0) sidx[b * NTOKS + p] = tok0;
        p += f0;
        if (f1) sidx[b * NTOKS + p] = tok0 + 1;
        p += f1;
        if (f2) sidx[b * NTOKS + p] = tok0 + 2;
        p += f2;
        if (f3) sidx[b * NTOKS + p] = tok0 + 3;
        base += tot;
        __syncthreads();
    }
}

// ---------------- AC_MSA via tensor-core MMA ----------------
__global__ void __launch_bounds__(256) acmsa_mma_kernel(
    const float* __restrict__ qkv, const int* __restrict__ sidx,
    float* __restrict__ ycat)
{
    __shared__ __align__(16) char smem_raw[27136];
    float* sQ = (float*)smem_raw;
    float* sK = (float*)smem_raw;
    __nv_bfloat16* sVT = (__nv_bfloat16*)(smem_raw + 18432);
    uint32_t* vtw = (uint32_t*)(smem_raw + 18432);

    int g = blockIdx.x, head = blockIdx.y, b = blockIdx.z;
    int tid = threadIdx.x;
    int warp = tid >> 5, lane = tid & 31;
    int grp = lane >> 2, qid = lane & 3;
    int q0 = warp * 16;
    const int* sp = sidx + b * NTOKS + g * GS;

    {
        int r = tid >> 1, off = (tid & 1) * 16;
        int tok = sp[r];
        const float4* src = (const float4*)(qkv + ((size_t)(b * NTOKS + tok)) * H3
                                            + head * HD + off);
        #pragma unroll
        for (int u = 0; u < 4; u++) {
            float4 v = src[u];
            float* d = sQ + r * 36 + off + u * 4;
            d[0] = v.x * 0.17677669529663687f;
            d[1] = v.y * 0.17677669529663687f;
            d[2] = v.z * 0.17677669529663687f;
            d[3] = v.w * 0.17677669529663687f;
        }
    }
    __syncthreads();

    uint32_t qa[4][4];
    #pragma unroll
    for (int ks = 0; ks < 4; ks++) {
        qa[ks][0] = f2tf(sQ[(q0 + grp    ) * 36 + ks * 8 + qid    ]);
        qa[ks][1] = f2tf(sQ[(q0 + grp + 8) * 36 + ks * 8 + qid    ]);
        qa[ks][2] = f2tf(sQ[(q0 + grp    ) * 36 + ks * 8 + qid + 4]);
        qa[ks][3] = f2tf(sQ[(q0 + grp + 8) * 36 + ks * 8 + qid + 4]);
    }
    int tok0 = sp[q0 + grp], tok1 = sp[q0 + grp + 8];

    float o[4][4];
    #pragma unroll
    for (int nt = 0; nt < 4; nt++)
        #pragma unroll
        for (int r = 0; r < 4; r++) o[nt][r] = 0.f;
    float m0v = -1e30f, m1v = -1e30f, l0 = 0.f, l1 = 0.f;
    __syncthreads();

    {
        int key = tid >> 1, part = tid & 1;
        int tok = sp[key];
        const float* basep = qkv + ((size_t)(b * NTOKS + tok)) * H3 + head * HD;
        const float4* ksrc = (const float4*)(basep + DIM + part * 16);
        float* kd = sK + key * 36 + part * 16;
        #pragma unroll
        for (int u = 0; u < 4; u++) {
            float4 kv = ksrc[u];
            kd[u * 4 + 0] = kv.x; kd[u * 4 + 1] = kv.y;
            kd[u * 4 + 2] = kv.z; kd[u * 4 + 3] = kv.w;
        }
        const float4* vsrc = (const float4*)(basep + 2 * DIM + part * 16);
        int d0 = part * 16;
        #pragma unroll
        for (int u = 0; u < 4; u++) {
            float4 vv = vsrc[u];
            sVT[(d0 + u * 4 + 0) * 136 + key] = __float2bfloat16(vv.x);
            sVT[(d0 + u * 4 + 1) * 136 + key] = __float2bfloat16(vv.y);
            sVT[(d0 + u * 4 + 2) * 136 + key] = __float2bfloat16(vv.z);
            sVT[(d0 + u * 4 + 3) * 136 + key] = __float2bfloat16(vv.w);
        }
    }
    __syncthreads();

    for (int kc = 0; kc < 4; kc++) {
        float s[4][4];
        #pragma unroll
        for (int nt = 0; nt < 4; nt++)
            #pragma unroll
            for (int r = 0; r < 4; r++) s[nt][r] = 0.f;
        #pragma unroll
        for (int nt = 0; nt < 4; nt++) {
            int krow = (kc * 32 + nt * 8 + grp) * 36;
            #pragma unroll
            for (int ks = 0; ks < 4; ks++) {
                uint32_t b0 = f2tf(sK[krow + ks * 8 + qid]);
                uint32_t b1 = f2tf(sK[krow + ks * 8 + qid + 4]);
                mma_tf32(s[nt], qa[ks][0], qa[ks][1], qa[ks][2], qa[ks][3], b0, b1);
            }
        }
        float mx0 = fmaxf(fmaxf(s[0][0], s[0][1]), fmaxf(s[1][0], s[1][1]));
        mx0 = fmaxf(mx0, fmaxf(fmaxf(s[2][0], s[2][1]), fmaxf(s[3][0], s[3][1])));
        float mx1 = fmaxf(fmaxf(s[0][2], s[0][3]), fmaxf(s[1][2], s[1][3]));
        mx1 = fmaxf(mx1, fmaxf(fmaxf(s[2][2], s[2][3]), fmaxf(s[3][2], s[3][3])));
        mx0 = fmaxf(mx0, __shfl_xor_sync(0xffffffffu, mx0, 1));
        mx0 = fmaxf(mx0, __shfl_xor_sync(0xffffffffu, mx0, 2));
        mx1 = fmaxf(mx1, __shfl_xor_sync(0xffffffffu, mx1, 1));
        mx1 = fmaxf(mx1, __shfl_xor_sync(0xffffffffu, mx1, 2));
        float mn0 = fmaxf(m0v, mx0), mn1 = fmaxf(m1v, mx1);
        float f0 = fexp(m0v - mn0), f1 = fexp(m1v - mn1);
        m0v = mn0; m1v = mn1;
        l0 *= f0; l1 *= f1;
        #pragma unroll
        for (int nt = 0; nt < 4; nt++) {
            o[nt][0] *= f0; o[nt][1] *= f0;
            o[nt][2] *= f1; o[nt][3] *= f1;
        }
        float ps0 = 0.f, ps1 = 0.f;
        #pragma unroll
        for (int nt = 0; nt < 4; nt++) {
            s[nt][0] = fexp(s[nt][0] - mn0); ps0 += s[nt][0];
            s[nt][1] = fexp(s[nt][1] - mn0); ps0 += s[nt][1];
            s[nt][2] = fexp(s[nt][2] - mn1); ps1 += s[nt][2];
            s[nt][3] = fexp(s[nt][3] - mn1); ps1 += s[nt][3];
        }
        l0 += ps0; l1 += ps1;
        #pragma unroll
        for (int ks = 0; ks < 2; ks++) {
            uint32_t a0 = pkbf(s[2 * ks][0],     s[2 * ks][1]);
            uint32_t a1 = pkbf(s[2 * ks][2],     s[2 * ks][3]);
            uint32_t a2 = pkbf(s[2 * ks + 1][0], s[2 * ks + 1][1]);
            uint32_t a3 = pkbf(s[2 * ks + 1][2], s[2 * ks + 1][3]);
            #pragma unroll
            for (int ntd = 0; ntd < 4; ntd++) {
                int base = (ntd * 8 + grp) * 68 + kc * 16 + ks * 8 + qid;
                mma_bf16(o[ntd], a0, a1, a2, a3, vtw[base], vtw[base + 4]);
            }
        }
    }
    l0 += __shfl_xor_sync(0xffffffffu, l0, 1);
    l0 += __shfl_xor_sync(0xffffffffu, l0, 2);
    l1 += __shfl_xor_sync(0xffffffffu, l1, 1);
    l1 += __shfl_xor_sync(0xffffffffu, l1, 2);
    float inv0 = 1.0f / l0, inv1 = 1.0f / l1;
    float* out0 = ycat + ((size_t)(b * NTOKS + tok0)) * YC + DIM + head * HD;
    float* out1 = ycat + ((size_t)(b * NTOKS + tok1)) * YC + DIM + head * HD;
    #pragma unroll
    for (int nt = 0; nt < 4; nt++) {
        float2 w0; w0.x = o[nt][0] * inv0; w0.y = o[nt][1] * inv0;
        float2 w1; w1.x = o[nt][2] * inv1; w1.y = o[nt][3] * inv1;
        *(float2*)(out0 + nt * 8 + 2 * qid) = w0;
        *(float2*)(out1 + nt * 8 + 2 * qid) = w1;
    }
}

// ---------------- transposed relative position bias ----------------
__global__ void rpbt_kernel(const int* __restrict__ rpi, const float* __restrict__ table,
                            float* __restrict__ rpbT) {
    int idx = blockIdx.x * 256 + threadIdx.x;
    if (idx >= NHEAD * WIN * WIN) return;
    int h = idx >> 16;
    int r = idx & 65535;
    int kj = r >> 8, qi = r & 255;
    rpbT[idx] = table[rpi[qi * WIN + kj] * NHEAD + h];
}

// ---------------- shifted-window attention via MMA ----------------
__global__ void __launch_bounds__(512) winattn_mma_kernel(
    const float* __restrict__ qkv, const float* __restrict__ mask,
    const float* __restrict__ rpbT, float* __restrict__ ycat)
{
    __shared__ __align__(16) char smem_raw[36864];
    float* sQ = (float*)smem_raw;
    float* sK = (float*)smem_raw;
    __nv_bfloat16* sVT = (__nv_bfloat16*)(smem_raw + 18432);
    uint32_t* vtw = (uint32_t*)(smem_raw + 18432);

    int wl = blockIdx.x, head = blockIdx.y, b = blockIdx.z;
    int wy = wl >> 3, wx = wl & 7;
    int tid = threadIdx.x;
    int warp = tid >> 5, lane = tid & 31;
    int grp = lane >> 2, qid = lane & 3;
    int q0 = warp * 16;

    {
        int r = tid >> 1, off = (tid & 1) * 16;
        int i = r >> 4, j = r & 15;
        int n = (((wy * WS + i + SS) & 127) << 7) | ((wx * WS + j + SS) & 127);
        const float4* src = (const float4*)(qkv + ((size_t)(b * NTOKS + n)) * H3
                                            + head * HD + off);
        #pragma unroll
        for (int u = 0; u < 4; u++) {
            float4 v = src[u];
            float* d = sQ + r * 36 + off + u * 4;
            d[0] = v.x * 0.17677669529663687f;
            d[1] = v.y * 0.17677669529663687f;
            d[2] = v.z * 0.17677669529663687f;
            d[3] = v.w * 0.17677669529663687f;
        }
    }
    __syncthreads();

    uint32_t qa[4][4];
    #pragma unroll
    for (int ks = 0; ks < 4; ks++) {
        qa[ks][0] = f2tf(sQ[(q0 + grp    ) * 36 + ks * 8 + qid    ]);
        qa[ks][1] = f2tf(sQ[(q0 + grp + 8) * 36 + ks * 8 + qid    ]);
        qa[ks][2] = f2tf(sQ[(q0 + grp    ) * 36 + ks * 8 + qid + 4]);
        qa[ks][3] = f2tf(sQ[(q0 + grp + 8) * 36 + ks * 8 + qid + 4]);
    }
    int r0 = q0 + grp, r1 = r0 + 8;
    int i0 = r0 >> 4, j0 = r0 & 15;
    int i1 = r1 >> 4, j1 = r1 & 15;
    int tok0 = (((wy * WS + i0 + SS) & 127) << 7) | ((wx * WS + j0 + SS) & 127);
    int tok1 = (((wy * WS + i1 + SS) & 127) << 7) | ((wx * WS + j1 + SS) & 127);
    const float* rpbh  = rpbT + (size_t)head * (WIN * WIN);
    const float* maskw = mask + (size_t)wl * (WIN * WIN);

    float o[4][4];
    #pragma unroll
    for (int nt = 0; nt < 4; nt++)
        #pragma unroll
        for (int r = 0; r < 4; r++) o[nt][r] = 0.f;
    float m0v = -1e30f, m1v = -1e30f, l0 = 0.f, l1 = 0.f;
    __syncthreads();

    for (int kt = 0; kt < 2; kt++) {
        {
            int key = tid >> 2, part = tid & 3;
            int p = kt * 128 + key;
            int pi = p >> 4, pj = p & 15;
            int np = (((wy * WS + pi + SS) & 127) << 7) | ((wx * WS + pj + SS) & 127);
            const float* basep = qkv + ((size_t)(b * NTOKS + np)) * H3 + head * HD;
            const float4* ksrc = (const float4*)(basep + DIM + part * 8);
            float4 k0 = ksrc[0], k1 = ksrc[1];
            float* kd = sK + key * 36 + part * 8;
            kd[0] = k0.x; kd[1] = k0.y; kd[2] = k0.z; kd[3] = k0.w;
            kd[4] = k1.x; kd[5] = k1.y; kd[6] = k1.z; kd[7] = k1.w;
            const float4* vsrc = (const float4*)(basep + 2 * DIM + part * 8);
            float4 v0 = vsrc[0], v1 = vsrc[1];
            int d0 = part * 8;
            sVT[(d0 + 0) * 136 + key] = __float2bfloat16(v0.x);
            sVT[(d0 + 1) * 136 + key] = __float2bfloat16(v0.y);
            sVT[(d0 + 2) * 136 + key] = __float2bfloat16(v0.z);
            sVT[(d0 + 3) * 136 + key] = __float2bfloat16(v0.w);
            sVT[(d0 + 4) * 136 + key] = __float2bfloat16(v1.x);
            sVT[(d0 + 5) * 136 + key] = __float2bfloat16(v1.y);
            sVT[(d0 + 6) * 136 + key] = __float2bfloat16(v1.z);
            sVT[(d0 + 7) * 136 + key] = __float2bfloat16(v1.w);
        }
        __syncthreads();

        for (int kc = 0; kc < 4; kc++) {
            int kbase = kt * 128 + kc * 32;
            float s[4][4];
            #pragma unroll
            for (int nt = 0; nt < 4; nt++)
                #pragma unroll
                for (int r = 0; r < 4; r++) s[nt][r] = 0.f;
            #pragma unroll
            for (int nt = 0; nt < 4; nt++) {
                int krow = (kc * 32 + nt * 8 + grp) * 36;
                #pragma unroll
                for (int ks = 0; ks < 4; ks++) {
                    uint32_t b0 = f2tf(sK[krow + ks * 8 + qid]);
                    uint32_t b1 = f2tf(sK[krow + ks * 8 + qid + 4]);
                    mma_tf32(s[nt], qa[ks][0], qa[ks][1], qa[ks][2], qa[ks][3], b0, b1);
                }
            }
            #pragma unroll
            for (int nt = 0; nt < 4; nt++) {
                int c0 = kbase + nt * 8 + 2 * qid;
                s[nt][0] += rpbh[c0 * WIN + r0] + maskw[c0 * WIN + r0];
                s[nt][1] += rpbh[(c0 + 1) * WIN + r0] + maskw[(c0 + 1) * WIN + r0];
                s[nt][2] += rpbh[c0 * WIN + r1] + maskw[c0 * WIN + r1];
                s[nt][3] += rpbh[(c0 + 1) * WIN + r1] + maskw[(c0 + 1) * WIN + r1];
            }
            float mx0 = fmaxf(fmaxf(s[0][0], s[0][1]), fmaxf(s[1][0], s[1][1]));
            mx0 = fmaxf(mx0, fmaxf(fmaxf(s[2][0], s[2][1]), fmaxf(s[3][0], s[3][1])));
            float mx1 = fmaxf(fmaxf(s[0][2], s[0][3]), fmaxf(s[1][2], s[1][3]));
            mx1 = fmaxf(mx1, fmaxf(fmaxf(s[2][2], s[2][3]), fmaxf(s[3][2], s[3][3])));
            mx0 = fmaxf(mx0, __shfl_xor_sync(0xffffffffu, mx0, 1));
            mx0 = fmaxf(mx0, __shfl_xor_sync(0xffffffffu, mx0, 2));
            mx1 = fmaxf(mx1, __shfl_xor_sync(0xffffffffu, mx1, 1));
            mx1 = fmaxf(mx1, __shfl_xor_sync(0xffffffffu, mx1, 2));
            float mn0 = fmaxf(m0v, mx0), mn1 = fmaxf(m1v, mx1);
            float f0 = fexp(m0v - mn0), f1 = fexp(m1v - mn1);
            m0v = mn0; m1v = mn1;
            l0 *= f0; l1 *= f1;
            #pragma unroll
            for (int nt = 0; nt < 4; nt++) {
                o[nt][0] *= f0; o[nt][1] *= f0;
                o[nt][2] *= f1; o[nt][3] *= f1;
            }
            float ps0 = 0.f, ps1 = 0.f;
            #pragma unroll
            for (int nt = 0; nt < 4; nt++) {
                s[nt][0] = fexp(s[nt][0] - mn0); ps0 += s[nt][0];
                s[nt][1] = fexp(s[nt][1] - mn0); ps0 += s[nt][1];
                s[nt][2] = fexp(s[nt][2] - mn1); ps1 += s[nt][2];
                s[nt][3] = fexp(s[nt][3] - mn1); ps1 += s[nt][3];
            }
            l0 += ps0; l1 += ps1;
            #pragma unroll
            for (int ks = 0; ks < 2; ks++) {
                uint32_t a0 = pkbf(s[2 * ks][0],     s[2 * ks][1]);
                uint32_t a1 = pkbf(s[2 * ks][2],     s[2 * ks][3]);
                uint32_t a2 = pkbf(s[2 * ks + 1][0], s[2 * ks + 1][1]);
                uint32_t a3 = pkbf(s[2 * ks + 1][2], s[2 * ks + 1][3]);
                #pragma unroll
                for (int ntd = 0; ntd < 4; ntd++) {
                    int base = (ntd * 8 + grp) * 68 + kc * 16 + ks * 8 + qid;
                    mma_bf16(o[ntd], a0, a1, a2, a3, vtw[base], vtw[base + 4]);
                }
            }
        }
        __syncthreads();
    }
    l0 += __shfl_xor_sync(0xffffffffu, l0, 1);
    l0 += __shfl_xor_sync(0xffffffffu, l0, 2);
    l1 += __shfl_xor_sync(0xffffffffu, l1, 1);
    l1 += __shfl_xor_sync(0xffffffffu, l1, 2);
    float inv0 = 1.0f / l0, inv1 = 1.0f / l1;
    float* out0 = ycat + ((size_t)(b * NTOKS + tok0)) * YC + head * HD;
    float* out1 = ycat + ((size_t)(b * NTOKS + tok1)) * YC + head * HD;
    #pragma unroll
    for (int nt = 0; nt < 4; nt++) {
        float2 w0; w0.x = o[nt][0] * inv0; w0.y = o[nt][1] * inv0;
        float2 w1; w1.x = o[nt][2] * inv1; w1.y = o[nt][3] * inv1;
        *(float2*)(out0 + nt * 8 + 2 * qid) = w0;
        *(float2*)(out1 + nt * 8 + 2 * qid) = w1;
    }
}

// ---------------- pack merged projection ----------------
__global__ void packproj_kernel(const float* __restrict__ ww, const float* __restrict__ wa,
                                const float* __restrict__ bw, const float* __restrict__ ba,
                                float* __restrict__ Bcat, float* __restrict__ bcat) {
    int idx = blockIdx.x * 256 + threadIdx.x;
    if (idx >= YC * DIM) return;
    int k = idx / DIM, n = idx % DIM;
    Bcat[idx] = (k < DIM) ? ww[k * DIM + n] : wa[(k - DIM) * DIM + n];
    if (idx < DIM) bcat[idx] = bw[idx] + ba[idx];
}

// ---------------- gather token-dict features (float4) ----------------
__global__ void gather_td_kernel(const float* __restrict__ tdf, const int* __restrict__ tkid,
                                 float* __restrict__ xc) {
    int idx = blockIdx.x * 256 + threadIdx.x;
    if (idx >= TOT * (DTD / 4)) return;
    int tok = idx >> 4, j = idx & 15;
    int b = tok >> 14;
    const float4* src = (const float4*)tdf;
    float4* dst = (float4*)xc;
    dst[(size_t)tok * (CH / 4) + (MLPH / 4) + j] =
        src[((size_t)(b << 6) + tkid[tok]) * (DTD / 4) + j];
}

// ---------------- depthwise 5x5 conv: 2 channels x 4 y-outputs per thread ----------
__global__ void dwconv_kernel(const float* __restrict__ xc, const float* __restrict__ w,
                              const float* __restrict__ bias, float* __restrict__ sout) {
    int u = blockIdx.x * 256 + threadIdx.x;
    if (u >= TOT * CH / 8) return;
    int cp = u % (CH / 2);
    int c = cp * 2;
    int p4 = u / (CH / 2);
    int x = p4 & 127, y4 = (p4 >> 7) & 31, b = p4 >> 12;
    int y0 = y4 << 2;
    float2 wr[25];
    #pragma unroll
    for (int i = 0; i < 25; i++) wr[i] = *(const float2*)(w + i * CH + c);
    float2 acc[4];
    #pragma unroll
    for (int r = 0; r < 4; r++) { acc[r].x = 0.f; acc[r].y = 0.f; }
    #pragma unroll
    for (int ry = 0; ry < 8; ry++) {
        int yy = y0 + ry - 2;
        if ((unsigned)yy >= 128u) continue;
        #pragma unroll
        for (int dx = 0; dx < 5; dx++) {
            int xx = x + dx - 2;
            if ((unsigned)xx >= 128u) continue;
            float2 v = *(const float2*)(xc + (size_t)((b << 14) | (yy << 7) | xx) * CH + c);
            #pragma unroll
            for (int r = 0; r < 4; r++) {
                int dy = ry - r;
                if (dy >= 0 && dy < 5) {
                    float2 ww2 = wr[dy * 5 + dx];
                    acc[r].x = fmaf(v.x, ww2.x, acc[r].x);
                    acc[r].y = fmaf(v.y, ww2.y, acc[r].y);
                }
            }
        }
    }
    float2 bc = *(const float2*)(bias + c);
    #pragma unroll
    for (int r = 0; r < 4; r++) {
        size_t idx = (size_t)((b << 14) | ((y0 + r) << 7) | x) * CH + c;
        float2 xv = *(const float2*)(xc + idx);
        float2 ov;
        ov.x = xv.x + gelu_f(acc[r].x + bc.x);
        ov.y = xv.y + gelu_f(acc[r].y + bc.y);
        *(float2*)(sout + idx) = ov;
    }
}

// ---------------- host side ----------------
static void sgemm(int epi, const float* A, const float* B, const float* bias, const float* D,
                  float* C, int M, int N, int K, int ldc, int ldd,
                  int nz = 1, size_t sA = 0, size_t sB = 0, size_t sD = 0, size_t sC = 0) {
    dim3 grid(N / 64, M / 128, nz), block(256);
    if (epi == 0)      tgemm_k<0><<<grid, block>>>(A, B, bias, D, C, M, N, K, ldc, ldd, sA, sB, sD, sC);
    else if (epi == 1) tgemm_k<1><<<grid, block>>>(A, B, bias, D, C, M, N, K, ldc, ldd, sA, sB, sD, sC);
    else               tgemm_k<2><<<grid, block>>>(A, B, bias, D, C, M, N, K, ldc, ldd, sA, sB, sD, sC);
}

extern "C" void kernel_launch(void* const* d_in, const int* in_sizes, int n_in,
                              void* d_out, int out_size) {
    (void)in_sizes; (void)out_size;
    const float* x         = (const float*)d_in[0];
    const float* td        = (const float*)d_in[1];
    const float* attn_mask = (const float*)d_in[2];
    const int*   rpi       = (const int*)  d_in[3];
    int base = (n_in >= 32) ? 6 : 4;
    const float* norm1_g    = (const float*)d_in[base + 0];
    const float* norm1_b    = (const float*)d_in[base + 1];
    const float* norm2_g    = (const float*)d_in[base + 2];
    const float* norm2_b    = (const float*)d_in[base + 3];
    const float* wqkv_w     = (const float*)d_in[base + 4];
    const float* wqkv_b     = (const float*)d_in[base + 5];
    const float* wq_w       = (const float*)d_in[base + 6];
    const float* wq_b       = (const float*)d_in[base + 7];
    const float* wk_w       = (const float*)d_in[base + 8];
    const float* wk_b       = (const float*)d_in[base + 9];
    const float* wv_w       = (const float*)d_in[base + 10];
    const float* wv_b       = (const float*)d_in[base + 11];
    const float* atd_scale  = (const float*)d_in[base + 12];
    const float* aca_proj_w = (const float*)d_in[base + 13];
    const float* aca_proj_b = (const float*)d_in[base + 14];
    const float* rpb_table  = (const float*)d_in[base + 15];
    const float* win_proj_w = (const float*)d_in[base + 16];
    const float* win_proj_b = (const float*)d_in[base + 17];
    const float* fc_td_w    = (const float*)d_in[base + 18];
    const float* fc_td_b    = (const float*)d_in[base + 19];
    const float* fc1_w      = (const float*)d_in[base + 20];
    const float* fc1_b      = (const float*)d_in[base + 21];
    const float* dw_w       = (const float*)d_in[base + 22];
    const float* dw_b       = (const float*)d_in[base + 23];
    const float* fc2_w      = (const float*)d_in[base + 24];
    const float* fc2_b      = (const float*)d_in[base + 25];

    float *xn, *qkv, *qb, *kn, *vb, *tdf, *sim, *ycat, *xs, *rpbT, *xc, *sb, *bcat, *bcatb;
    int *tkid, *sidx, *off;
    cudaGetSymbolAddress((void**)&xn,    g_xn);
    cudaGetSymbolAddress((void**)&qkv,   g_qkv);
    cudaGetSymbolAddress((void**)&qb,    g_q);
    cudaGetSymbolAddress((void**)&kn,    g_kn);
    cudaGetSymbolAddress((void**)&vb,    g_v);
    cudaGetSymbolAddress((void**)&tdf,   g_tdf);
    cudaGetSymbolAddress((void**)&sim,   g_sim);
    cudaGetSymbolAddress((void**)&tkid,  g_tkid);
    cudaGetSymbolAddress((void**)&sidx,  g_sidx);
    cudaGetSymbolAddress((void**)&off,   g_off);
    cudaGetSymbolAddress((void**)&ycat,  g_ycat);
    cudaGetSymbolAddress((void**)&xs,    g_xs);
    cudaGetSymbolAddress((void**)&rpbT,  g_rpbT);
    cudaGetSymbolAddress((void**)&xc,    g_xc);
    cudaGetSymbolAddress((void**)&sb,    g_s);
    cudaGetSymbolAddress((void**)&bcat,  g_bcat);
    cudaGetSymbolAddress((void**)&bcatb, g_bcatb);

    bool fork = (g_s2 != nullptr && g_ev1 != nullptr && g_ev2 != nullptr);

    // 1) LN1 + qkv GEMM on main stream
    ln_kernel<<<TOT / 8, 256>>>(x, norm1_g, norm1_b, xn);
    sgemm(0, xn, wqkv_w, wqkv_b, nullptr, qkv, TOT, H3, DIM, H3, 0);

    if (fork) {
        cudaEventRecord(g_ev1, 0);
        cudaStreamWaitEvent(g_s2, g_ev1, 0);
        packproj_kernel<<<(YC * DIM + 255) / 256, 256, 0, g_s2>>>(
            win_proj_w, aca_proj_w, win_proj_b, aca_proj_b, bcat, bcatb);
        rpbt_kernel<<<(NHEAD * WIN * WIN + 255) / 256, 256, 0, g_s2>>>(rpi, rpb_table, rpbT);
        winattn_mma_kernel<<<dim3(NWIN, NHEAD, BATCH), 512, 0, g_s2>>>(
            qkv, attn_mask, rpbT, ycat);
        cudaEventRecord(g_ev2, g_s2);
    }

    // main stream: ATD chain
    qproj_kernel<<<(TOT * RD + 255) / 256, 256>>>(xn, wq_w, wq_b, qb);
    tdprep_kernel<<<BATCH * NDICT, DIM>>>(td, wk_w, wk_b, wv_w, wv_b, fc_td_w, fc_td_b,
                                          kn, vb, tdf);
    atd_kernel<<<TOT, NDICT>>>(qb, kn, atd_scale, sim, tkid);
    sgemm(2, sim, vb, nullptr, x, xs, NTOKS, DIM, NDICT, DIM, DIM,
          BATCH, (size_t)NTOKS * NDICT, (size_t)NDICT * DIM,
          (size_t)NTOKS * DIM, (size_t)NTOKS * DIM);
    hist_kernel<<<BATCH, 256>>>(tkid, off);
    scatter_kernel<<<BATCH * NDICT, 256>>>(tkid, off, sidx);
    acmsa_mma_kernel<<<dim3(NG, NHEAD, BATCH), 256>>>(qkv, sidx, ycat);

    if (fork) {
        cudaStreamWaitEvent(0, g_ev2, 0);   // join
    } else {
        packproj_kernel<<<(YC * DIM + 255) / 256, 256>>>(win_proj_w, aca_proj_w,
                                                         win_proj_b, aca_proj_b, bcat, bcatb);
        rpbt_kernel<<<(NHEAD * WIN * WIN + 255) / 256, 256>>>(rpi, rpb_table, rpbT);
        winattn_mma_kernel<<<dim3(NWIN, NHEAD, BATCH), 512>>>(qkv, attn_mask, rpbT, ycat);
    }

    // merged projection + FFN tail
    sgemm(2, ycat, bcat, bcatb, xs, xs, TOT, DIM, YC, DIM, DIM);
    ln_kernel<<<TOT / 8, 256>>>(xs, norm2_g, norm2_b, xn);
    sgemm(1, xn, fc1_w, fc1_b, nullptr, xc, TOT, MLPH, DIM, CH, 0);
    gather_td_kernel<<<(TOT * (DTD / 4) + 255) / 256, 256>>>(tdf, tkid, xc);
    dwconv_kernel<<<(TOT * CH / 8 + 255) / 256, 256>>>(xc, dw_w, dw_b, sb);
    sgemm(2, sb, fc2_w, fc2_b, xs, (float*)d_out, TOT, DIM, CH, DIM, DIM);
}